// round 10
// baseline (speedup 1.0000x reference)
#include <cuda_runtime.h>
#include <cuda_fp16.h>
#include <math.h>
#include <stdint.h>

#define D_MODEL 2048
#define BATCH   2
#define SEQ     2048
#define MROWS   (BATCH * SEQ)                 // 4096
#define ELEMS   ((size_t)MROWS * D_MODEL)     // 8388608
#define WELEMS  ((size_t)D_MODEL * D_MODEL)   // 4194304

// ---------------------------------------------------------------------------
// Device scratch (allocation-free contract) — all single fp16
// ---------------------------------------------------------------------------
__device__ __half g_xs[ELEMS];                      // x fp16
__device__ __half g_Wt[4 * WELEMS];                 // W^T fp16, [n][k]
__device__ __half g_Qs[ELEMS];                      // Q
__device__ __half g_Ks[ELEMS];                      // K
__device__ __half g_Vt[ELEMS];                      // V^T: [b][d][s]
__device__ float  g_S [(size_t)BATCH * SEQ * SEQ];  // scores fp32
__device__ __half g_Ps[(size_t)BATCH * SEQ * SEQ];  // softmax(P)
__device__ __half g_Os[ELEMS];                      // attn output

// ---------------------------------------------------------------------------
// Helpers
// ---------------------------------------------------------------------------
__device__ __forceinline__ uint32_t s2u(const void* p) {
    return (uint32_t)__cvta_generic_to_shared(p);
}
__device__ __forceinline__ void cp16(uint32_t dst, const void* src) {
    asm volatile("cp.async.cg.shared.global [%0], [%1], 16;\n"
                 :: "r"(dst), "l"(__cvta_generic_to_global(src)));
}
__device__ __forceinline__ void cp_commit() { asm volatile("cp.async.commit_group;"); }
template<int N> __device__ __forceinline__ void cp_wait() {
    asm volatile("cp.async.wait_group %0;" :: "n"(N));
}
__device__ __forceinline__ void ldm_x4(uint32_t* r, uint32_t addr) {
    asm volatile("ldmatrix.sync.aligned.m8n8.x4.shared.b16 {%0,%1,%2,%3}, [%4];"
                 : "=r"(r[0]), "=r"(r[1]), "=r"(r[2]), "=r"(r[3]) : "r"(addr));
}
__device__ __forceinline__ void mma_f16(float* d, const uint32_t* a,
                                        uint32_t b0, uint32_t b1) {
    asm volatile(
        "mma.sync.aligned.m16n8k16.row.col.f32.f16.f16.f32 "
        "{%0,%1,%2,%3}, {%4,%5,%6,%7}, {%8,%9}, {%0,%1,%2,%3};"
        : "+f"(d[0]), "+f"(d[1]), "+f"(d[2]), "+f"(d[3])
        : "r"(a[0]), "r"(a[1]), "r"(a[2]), "r"(a[3]), "r"(b0), "r"(b1));
}
__device__ __forceinline__ unsigned short h1(float v) {
    __half hh = __float2half_rn(v);
    return *reinterpret_cast<unsigned short*>(&hh);
}

// ---------------------------------------------------------------------------
// Tiling: CTA tile 128x128, 256 threads = 8 warps in 2(M) x 4(N) grid,
// warp tile 64(M) x 32(N). K-chunk 32, 4-stage cp.async. 2 CTAs/SM.
// Smem rows padded to 80 B -> conflict-free ldmatrix.
// ---------------------------------------------------------------------------
#define KC      32
#define STAGES  4
#define ROWB    80
#define TILEB   (128 * ROWB)      // 10240 per operand array
#define STG     (2 * TILEB)       // 20480 per stage (A, B)
#define NCH     (2048 / KC)       // 64
#define SMEM_SZ (STAGES * STG)    // 81920
#define GTHR    256

struct MmaCtx {
    float acc[4][4][4];
};

__device__ __forceinline__ void gemm_mainloop(
    MmaCtx& ctx, uint32_t sb, int tid, int wm, int wn, int lane,
    const __half* A0, const __half* B0, long rowA0, long colB0)
{
    // loads: 256 threads, 2 cp16 per array each (row = tid>>1, segs)
    const int lr  = tid >> 1;
    const int ls0 = (tid & 1) << 1;
    auto load_chunk = [&](int chunk, int stage) {
        const int k0 = chunk * KC;
        const uint32_t base = sb + (uint32_t)stage * STG;
        #pragma unroll
        for (int p = 0; p < 2; p++) {
            const int sg = ls0 + p;
            const uint32_t d = base + (uint32_t)(lr * ROWB + sg * 16);
            cp16(d,         A0 + (rowA0 + lr) * 2048 + k0 + sg * 8);
            cp16(d + TILEB, B0 + (colB0 + lr) * 2048 + k0 + sg * 8);
        }
    };

    const int fr  = lane & 15;
    const int fc  = (lane >> 4) << 4;
    const uint32_t aoff = (uint32_t)((wm * 64 + fr) * ROWB + fc);
    const uint32_t boff = (uint32_t)((wn * 32 + fr) * ROWB + fc);

    #pragma unroll
    for (int i = 0; i < 4; i++)
        #pragma unroll
        for (int j = 0; j < 4; j++)
            #pragma unroll
            for (int c = 0; c < 4; c++)
                ctx.acc[i][j][c] = 0.0f;

    load_chunk(0, 0); cp_commit();
    load_chunk(1, 1); cp_commit();
    load_chunk(2, 2); cp_commit();

    for (int i = 0; i < NCH; i++) {
        if (i < NCH - 2)       cp_wait<2>();
        else if (i == NCH - 2) cp_wait<1>();
        else                   cp_wait<0>();
        __syncthreads();

        if (i + STAGES - 1 < NCH) {
            load_chunk(i + STAGES - 1, (i + STAGES - 1) & (STAGES - 1));
            cp_commit();
        }

        const uint32_t base = sb + (uint32_t)(i & (STAGES - 1)) * STG;
        #pragma unroll
        for (int ks = 0; ks < 2; ks++) {
            uint32_t aa[4][4], bb[2][4];
            #pragma unroll
            for (int mf = 0; mf < 4; mf++) {
                uint32_t ad = base + aoff + (uint32_t)(mf * 16 * ROWB + ks * 32);
                ldm_x4(aa[mf], ad);
            }
            #pragma unroll
            for (int nf = 0; nf < 2; nf++) {
                uint32_t bd = base + TILEB + boff
                            + (uint32_t)(nf * 16 * ROWB + ks * 32);
                ldm_x4(bb[nf], bd);
            }
            #pragma unroll
            for (int mf = 0; mf < 4; mf++)
                #pragma unroll
                for (int j = 0; j < 4; j++) {
                    const int nf = j >> 1, o = j & 1;
                    mma_f16(ctx.acc[mf][j], aa[mf], bb[nf][o], bb[nf][o + 2]);
                }
        }
    }
    __syncthreads();
}

// ---------------------------------------------------------------------------
// Generic GEMM kernel (EPI: 0 = fp32*alpha -> Cf ; 2 = fp16 -> Ch)
// ---------------------------------------------------------------------------
template<int EPI>
__global__ void __launch_bounds__(GTHR, 2)
gemm_mma(const __half* __restrict__ A, const __half* __restrict__ B,
         float* __restrict__ Cf, __half* __restrict__ Ch,
         long sA, long sB, long sC, float alpha)
{
    extern __shared__ char smem[];
    const uint32_t sb = s2u(smem);
    const int tid  = threadIdx.x;
    const int warp = tid >> 5;
    const int lane = tid & 31;
    const int wm   = warp >> 2;          // 0..1
    const int wn   = warp & 3;           // 0..3

    const long rowA0 = (long)blockIdx.y * 128;
    const long colB0 = (long)blockIdx.x * 128;

    MmaCtx ctx;
    gemm_mainloop(ctx, sb, tid, wm, wn, lane,
                  A + (long)blockIdx.z * sA, B + (long)blockIdx.z * sB,
                  rowA0, colB0);

    const int er = lane >> 2;
    const int ec = (lane & 3) << 1;
    #pragma unroll
    for (int mf = 0; mf < 4; mf++) {
        const long m0 = rowA0 + wm * 64 + mf * 16 + er;
        #pragma unroll
        for (int j = 0; j < 4; j++) {
            const long n = colB0 + wn * 32 + j * 8 + ec;
            if (EPI == 0) {
                float* C = Cf + (long)blockIdx.z * sC;
                float2 v0 = make_float2(alpha * ctx.acc[mf][j][0], alpha * ctx.acc[mf][j][1]);
                float2 v1 = make_float2(alpha * ctx.acc[mf][j][2], alpha * ctx.acc[mf][j][3]);
                *reinterpret_cast<float2*>(C + m0 * 2048 + n)       = v0;
                *reinterpret_cast<float2*>(C + (m0 + 8) * 2048 + n) = v1;
            } else {
                unsigned short* C = (unsigned short*)Ch + (long)blockIdx.z * sC;
                ushort2 v0 = make_ushort2(h1(ctx.acc[mf][j][0]), h1(ctx.acc[mf][j][1]));
                ushort2 v1 = make_ushort2(h1(ctx.acc[mf][j][2]), h1(ctx.acc[mf][j][3]));
                *reinterpret_cast<ushort2*>(C + m0 * 2048 + n)       = v0;
                *reinterpret_cast<ushort2*>(C + (m0 + 8) * 2048 + n) = v1;
            }
        }
    }
}

// ---------------------------------------------------------------------------
// Merged Q/K/V projection kernel: grid.z = weight index (0=Q, 1=K, 2=V).
// z=0 -> Qs, z=1 -> Ks (row-major), z=2 -> V^T scatter [b][n][s].
// ---------------------------------------------------------------------------
__global__ void __launch_bounds__(GTHR, 2)
gemm_qkv(const __half* __restrict__ xs, const __half* __restrict__ Wt,
         __half* __restrict__ Qs, __half* __restrict__ Ks,
         __half* __restrict__ Vt)
{
    extern __shared__ char smem[];
    const uint32_t sb = s2u(smem);
    const int tid  = threadIdx.x;
    const int warp = tid >> 5;
    const int lane = tid & 31;
    const int wm   = warp >> 2;
    const int wn   = warp & 3;
    const int z    = blockIdx.z;

    const long rowA0 = (long)blockIdx.y * 128;
    const long colB0 = (long)blockIdx.x * 128;

    MmaCtx ctx;
    gemm_mainloop(ctx, sb, tid, wm, wn, lane,
                  xs, Wt + (long)z * (long)WELEMS, rowA0, colB0);

    const int er = lane >> 2;
    const int ec = (lane & 3) << 1;
    if (z < 2) {
        unsigned short* C = (unsigned short*)(z == 0 ? Qs : Ks);
        #pragma unroll
        for (int mf = 0; mf < 4; mf++) {
            const long m0 = rowA0 + wm * 64 + mf * 16 + er;
            #pragma unroll
            for (int j = 0; j < 4; j++) {
                const long n = colB0 + wn * 32 + j * 8 + ec;
                ushort2 v0 = make_ushort2(h1(ctx.acc[mf][j][0]), h1(ctx.acc[mf][j][1]));
                ushort2 v1 = make_ushort2(h1(ctx.acc[mf][j][2]), h1(ctx.acc[mf][j][3]));
                *reinterpret_cast<ushort2*>(C + m0 * 2048 + n)       = v0;
                *reinterpret_cast<ushort2*>(C + (m0 + 8) * 2048 + n) = v1;
            }
        }
    } else {
        // V^T scatter: element (m, n) -> [b][n][s], b = m>>11, s = m&2047
        unsigned short* C = (unsigned short*)Vt;
        #pragma unroll
        for (int mf = 0; mf < 4; mf++) {
            const long m0 = rowA0 + wm * 64 + mf * 16 + er;
            #pragma unroll
            for (int j = 0; j < 4; j++) {
                const long n = colB0 + wn * 32 + j * 8 + ec;
                #pragma unroll
                for (int c = 0; c < 4; c++) {
                    long m = m0 + (c >> 1) * 8;
                    long nn = n + (c & 1);
                    long b = m >> 11, sl = m & 2047;
                    C[b * 4194304 + nn * 2048 + sl] = h1(ctx.acc[mf][j][c]);
                }
            }
        }
    }
}

// ---------------------------------------------------------------------------
// Merged conversion kernel:
//   blocks [0, 8192):      x fp32 -> fp16 (1024 elems per block)
//   blocks [8192, 24576):  W transposes, 32x32 tiles; weight = (bid-8192)/4096
// ---------------------------------------------------------------------------
__global__ void __launch_bounds__(256)
convall_kernel(const float* __restrict__ x,
               const float* __restrict__ Wq, const float* __restrict__ Wk,
               const float* __restrict__ Wv, const float* __restrict__ Wo,
               __half* __restrict__ xs, __half* __restrict__ Wt)
{
    const int bid = blockIdx.x;
    if (bid < 8192) {
        size_t i = ((size_t)bid * 256 + threadIdx.x) * 4;
        float4 v = *reinterpret_cast<const float4*>(x + i);
        ushort4 H;
        H.x = h1(v.x); H.y = h1(v.y); H.z = h1(v.z); H.w = h1(v.w);
        *reinterpret_cast<ushort4*>((unsigned short*)xs + i) = H;
        return;
    }
    const int t = bid - 8192;
    const int w = t >> 12;               // weight index 0..3
    const int ti = t & 4095;             // tile index within weight
    const float* W = (w == 0) ? Wq : (w == 1) ? Wk : (w == 2) ? Wv : Wo;
    __half* T = Wt + (size_t)w * WELEMS;

    __shared__ float tt[32][33];
    const int bx = (ti & 63) * 32, by = (ti >> 6) * 32;
    const int tx = threadIdx.x & 31, ty = threadIdx.x >> 5;   // 32 x 8
    #pragma unroll
    for (int rr = 0; rr < 4; rr++)
        tt[ty + 8 * rr][tx] = W[(size_t)(by + ty + 8 * rr) * 2048 + bx + tx];
    __syncthreads();
    #pragma unroll
    for (int rr = 0; rr < 4; rr++) {
        size_t o = (size_t)(bx + ty + 8 * rr) * 2048 + by + tx;
        ((unsigned short*)T)[o] = h1(tt[tx][ty + 8 * rr]);
    }
}

// ---------------------------------------------------------------------------
// Row softmax (fp32 in) -> P fp16. One block per row of 2048.
// ---------------------------------------------------------------------------
__global__ void __launch_bounds__(256)
softmax_kernel(const float* __restrict__ S, __half* __restrict__ P)
{
    const float4* row = reinterpret_cast<const float4*>(S + (size_t)blockIdx.x * SEQ);
    const int tid = threadIdx.x, lane = tid & 31, wid = tid >> 5;

    float4 a = row[tid];
    float4 b = row[tid + 256];

    float m = fmaxf(fmaxf(fmaxf(a.x, a.y), fmaxf(a.z, a.w)),
                    fmaxf(fmaxf(b.x, b.y), fmaxf(b.z, b.w)));
    #pragma unroll
    for (int o = 16; o > 0; o >>= 1) m = fmaxf(m, __shfl_xor_sync(~0u, m, o));

    __shared__ float redm[8], reds[8];
    if (lane == 0) redm[wid] = m;
    __syncthreads();
    float bm = fmaxf(fmaxf(fmaxf(redm[0], redm[1]), fmaxf(redm[2], redm[3])),
                     fmaxf(fmaxf(redm[4], redm[5]), fmaxf(redm[6], redm[7])));

    a.x = expf(a.x - bm); a.y = expf(a.y - bm); a.z = expf(a.z - bm); a.w = expf(a.w - bm);
    b.x = expf(b.x - bm); b.y = expf(b.y - bm); b.z = expf(b.z - bm); b.w = expf(b.w - bm);

    float sm = a.x + a.y + a.z + a.w + b.x + b.y + b.z + b.w;
    #pragma unroll
    for (int o = 16; o > 0; o >>= 1) sm += __shfl_xor_sync(~0u, sm, o);
    if (lane == 0) reds[wid] = sm;
    __syncthreads();
    float bs = reds[0] + reds[1] + reds[2] + reds[3] + reds[4] + reds[5] + reds[6] + reds[7];
    float inv = 1.0f / bs;

    const size_t base = (size_t)blockIdx.x * SEQ;
    unsigned short* PP = (unsigned short*)P;
    ushort4 H;
    H.x = h1(a.x * inv); H.y = h1(a.y * inv);
    H.z = h1(a.z * inv); H.w = h1(a.w * inv);
    *reinterpret_cast<ushort4*>(PP + base + tid * 4) = H;
    H.x = h1(b.x * inv); H.y = h1(b.y * inv);
    H.z = h1(b.z * inv); H.w = h1(b.w * inv);
    *reinterpret_cast<ushort4*>(PP + base + (tid + 256) * 4) = H;
}

// ---------------------------------------------------------------------------
// Launch
// ---------------------------------------------------------------------------
extern "C" void kernel_launch(void* const* d_in, const int* in_sizes, int n_in,
                              void* d_out, int out_size)
{
    (void)in_sizes; (void)n_in; (void)out_size;
    const float* x  = (const float*)d_in[0];
    const float* Wq = (const float*)d_in[1];
    const float* Wk = (const float*)d_in[2];
    const float* Wv = (const float*)d_in[3];
    const float* Wo = (const float*)d_in[4];
    float* out = (float*)d_out;

    __half *xs, *Wt, *Qs, *Ks, *Vt, *Ps, *Os;
    float* S;
    cudaGetSymbolAddress((void**)&xs, g_xs);
    cudaGetSymbolAddress((void**)&Wt, g_Wt);
    cudaGetSymbolAddress((void**)&Qs, g_Qs);
    cudaGetSymbolAddress((void**)&Ks, g_Ks);
    cudaGetSymbolAddress((void**)&Vt, g_Vt);
    cudaGetSymbolAddress((void**)&S,  g_S);
    cudaGetSymbolAddress((void**)&Ps, g_Ps);
    cudaGetSymbolAddress((void**)&Os, g_Os);

    cudaFuncSetAttribute(gemm_mma<0>, cudaFuncAttributeMaxDynamicSharedMemorySize, SMEM_SZ);
    cudaFuncSetAttribute(gemm_mma<2>, cudaFuncAttributeMaxDynamicSharedMemorySize, SMEM_SZ);
    cudaFuncSetAttribute(gemm_qkv,    cudaFuncAttributeMaxDynamicSharedMemorySize, SMEM_SZ);

    const float scale = 1.0f / sqrtf((float)D_MODEL);
    const long sBSS = (long)SEQ * SEQ;          // 4194304
    const long sSD  = (long)SEQ * D_MODEL;      // 4194304

    // all conversions in one launch (x conv + 4 weight transposes)
    convall_kernel<<<24576, 256>>>(x, Wq, Wk, Wv, Wo, xs, Wt);

    const dim3 gQKV(D_MODEL / 128, MROWS / 128, 3);    // (16, 32, 3) = 1536 CTAs
    const dim3 gProj(D_MODEL / 128, MROWS / 128, 1);   // (16, 32) = 512
    const dim3 gAttn(SEQ / 128, SEQ / 128, BATCH);     // (16, 16, 2) = 512

    // Q, K, V projections in one launch
    gemm_qkv<<<gQKV, GTHR, SMEM_SZ>>>(xs, Wt, Qs, Ks, Vt);
    // scores = scale * Q @ K^T  (fp32 epilogue)
    gemm_mma<0><<<gAttn, GTHR, SMEM_SZ>>>(Qs, Ks,
                                          S, nullptr, sSD, sSD, sBSS, scale);
    // softmax -> P fp16
    softmax_kernel<<<BATCH * SEQ, 256>>>(S, Ps);
    // O = P @ V  (B operand = V^T)
    gemm_mma<2><<<gAttn, GTHR, SMEM_SZ>>>(Ps, Vt,
                                          nullptr, Os, sBSS, sSD, sSD, 1.0f);
    // out = O @ W_o  (fp32 epilogue)
    gemm_mma<0><<<gProj, GTHR, SMEM_SZ>>>(Os, Wt + 3 * WELEMS,
                                          out, nullptr, 0, 0, 0, 1.0f);
}

// round 11
// speedup vs baseline: 1.0247x; 1.0247x over previous
#include <cuda_runtime.h>
#include <cuda_fp16.h>
#include <math.h>
#include <stdint.h>

#define D_MODEL 2048
#define BATCH   2
#define SEQ     2048
#define MROWS   (BATCH * SEQ)                 // 4096
#define ELEMS   ((size_t)MROWS * D_MODEL)     // 8388608
#define WELEMS  ((size_t)D_MODEL * D_MODEL)   // 4194304

// ---------------------------------------------------------------------------
// Device scratch (allocation-free contract) — all single fp16
// ---------------------------------------------------------------------------
__device__ __half g_xs[ELEMS];                      // x fp16
__device__ __half g_Wt[4 * WELEMS];                 // W^T fp16, [n][k]
__device__ __half g_Qs[ELEMS];                      // Q
__device__ __half g_Ks[ELEMS];                      // K
__device__ __half g_Vt[ELEMS];                      // V^T: [b][d][s]
__device__ float  g_S [(size_t)BATCH * SEQ * SEQ];  // scores fp32
__device__ __half g_Ps[(size_t)BATCH * SEQ * SEQ];  // softmax(P)
__device__ __half g_Os[ELEMS];                      // attn output

// ---------------------------------------------------------------------------
// Helpers
// ---------------------------------------------------------------------------
__device__ __forceinline__ uint32_t s2u(const void* p) {
    return (uint32_t)__cvta_generic_to_shared(p);
}
__device__ __forceinline__ void cp16(uint32_t dst, const void* src) {
    asm volatile("cp.async.cg.shared.global [%0], [%1], 16;\n"
                 :: "r"(dst), "l"(__cvta_generic_to_global(src)));
}
__device__ __forceinline__ void cp_commit() { asm volatile("cp.async.commit_group;"); }
template<int N> __device__ __forceinline__ void cp_wait() {
    asm volatile("cp.async.wait_group %0;" :: "n"(N));
}
__device__ __forceinline__ void ldm_x4(uint32_t* r, uint32_t addr) {
    asm volatile("ldmatrix.sync.aligned.m8n8.x4.shared.b16 {%0,%1,%2,%3}, [%4];"
                 : "=r"(r[0]), "=r"(r[1]), "=r"(r[2]), "=r"(r[3]) : "r"(addr));
}
__device__ __forceinline__ void mma_f16(float* d, const uint32_t* a,
                                        uint32_t b0, uint32_t b1) {
    asm volatile(
        "mma.sync.aligned.m16n8k16.row.col.f32.f16.f16.f32 "
        "{%0,%1,%2,%3}, {%4,%5,%6,%7}, {%8,%9}, {%0,%1,%2,%3};"
        : "+f"(d[0]), "+f"(d[1]), "+f"(d[2]), "+f"(d[3])
        : "r"(a[0]), "r"(a[1]), "r"(a[2]), "r"(a[3]), "r"(b0), "r"(b1));
}
__device__ __forceinline__ unsigned short h1(float v) {
    __half hh = __float2half_rn(v);
    return *reinterpret_cast<unsigned short*>(&hh);
}

// ---------------------------------------------------------------------------
// Tiling: CTA tile 128x128, 512 threads = 16 warps in 4x4 grid,
// warp tile 32(M) x 32(N). K-chunk 64 (halves barrier count vs KC=32),
// 4-stage cp.async, 1 CTA/SM.
// Smem rows: 128 B data + 16 B pad = 144 B stride. 144/16 = 9 (odd) ->
// 8 consecutive rows map to 8 distinct 16B bank groups: ldmatrix conflict-free.
// ---------------------------------------------------------------------------
#define KC      64
#define STAGES  4
#define ROWB    144
#define TILEB   (128 * ROWB)      // 18432 per operand array
#define STG     (2 * TILEB)       // 36864 per stage (A, B)
#define NCH     (2048 / KC)       // 32
#define SMEM_SZ (STAGES * STG)    // 147456
#define GTHR    512

struct MmaCtx {
    float acc[2][4][4];
};

__device__ __forceinline__ void gemm_mainloop(
    MmaCtx& ctx, uint32_t sb, int tid, int wm, int wn, int lane,
    const __half* A0, const __half* B0, long rowA0, long colB0)
{
    // loads: 1024 16B segments per array (128 rows x 8 segs); 2 per thread/array
    const int lr  = tid >> 2;            // row 0..127
    const int ls0 = tid & 3;             // seg ls0 and ls0+4
    auto load_chunk = [&](int chunk, int stage) {
        const int k0 = chunk * KC;
        const uint32_t base = sb + (uint32_t)stage * STG;
        #pragma unroll
        for (int p = 0; p < 2; p++) {
            const int sg = ls0 + p * 4;  // 0..7
            const uint32_t d = base + (uint32_t)(lr * ROWB + sg * 16);
            cp16(d,         A0 + (rowA0 + lr) * 2048 + k0 + sg * 8);
            cp16(d + TILEB, B0 + (colB0 + lr) * 2048 + k0 + sg * 8);
        }
    };

    const int fr  = lane & 15;
    const int fc  = (lane >> 4) << 4;    // byte col 0 or 16
    const uint32_t aoff = (uint32_t)((wm * 32 + fr) * ROWB + fc);
    const uint32_t boff = (uint32_t)((wn * 32 + fr) * ROWB + fc);

    #pragma unroll
    for (int i = 0; i < 2; i++)
        #pragma unroll
        for (int j = 0; j < 4; j++)
            #pragma unroll
            for (int c = 0; c < 4; c++)
                ctx.acc[i][j][c] = 0.0f;

    load_chunk(0, 0); cp_commit();
    load_chunk(1, 1); cp_commit();
    load_chunk(2, 2); cp_commit();

    for (int i = 0; i < NCH; i++) {
        if (i < NCH - 2)       cp_wait<2>();
        else if (i == NCH - 2) cp_wait<1>();
        else                   cp_wait<0>();
        __syncthreads();

        if (i + STAGES - 1 < NCH) {
            load_chunk(i + STAGES - 1, (i + STAGES - 1) & (STAGES - 1));
            cp_commit();
        }

        const uint32_t base = sb + (uint32_t)(i & (STAGES - 1)) * STG;
        #pragma unroll
        for (int ks = 0; ks < 4; ks++) {
            uint32_t aa[2][4], bb[2][4];
            #pragma unroll
            for (int mf = 0; mf < 2; mf++) {
                uint32_t ad = base + aoff + (uint32_t)(mf * 16 * ROWB + ks * 32);
                ldm_x4(aa[mf], ad);
            }
            #pragma unroll
            for (int nf = 0; nf < 2; nf++) {
                uint32_t bd = base + TILEB + boff
                            + (uint32_t)(nf * 16 * ROWB + ks * 32);
                ldm_x4(bb[nf], bd);
            }
            #pragma unroll
            for (int mf = 0; mf < 2; mf++)
                #pragma unroll
                for (int j = 0; j < 4; j++) {
                    const int nf = j >> 1, o = j & 1;
                    mma_f16(ctx.acc[mf][j], aa[mf], bb[nf][o], bb[nf][o + 2]);
                }
        }
    }
    __syncthreads();
}

// ---------------------------------------------------------------------------
// Generic GEMM kernel (EPI: 0 = fp32*alpha -> Cf ; 2 = fp16 -> Ch)
// ---------------------------------------------------------------------------
template<int EPI>
__global__ void __launch_bounds__(GTHR, 1)
gemm_mma(const __half* __restrict__ A, const __half* __restrict__ B,
         float* __restrict__ Cf, __half* __restrict__ Ch,
         long sA, long sB, long sC, float alpha)
{
    extern __shared__ char smem[];
    const uint32_t sb = s2u(smem);
    const int tid  = threadIdx.x;
    const int warp = tid >> 5;
    const int lane = tid & 31;
    const int wm   = warp & 3;
    const int wn   = warp >> 2;

    const long rowA0 = (long)blockIdx.y * 128;
    const long colB0 = (long)blockIdx.x * 128;

    MmaCtx ctx;
    gemm_mainloop(ctx, sb, tid, wm, wn, lane,
                  A + (long)blockIdx.z * sA, B + (long)blockIdx.z * sB,
                  rowA0, colB0);

    const int er = lane >> 2;
    const int ec = (lane & 3) << 1;
    #pragma unroll
    for (int mf = 0; mf < 2; mf++) {
        const long m0 = rowA0 + wm * 32 + mf * 16 + er;
        #pragma unroll
        for (int j = 0; j < 4; j++) {
            const long n = colB0 + wn * 32 + j * 8 + ec;
            if (EPI == 0) {
                float* C = Cf + (long)blockIdx.z * sC;
                float2 v0 = make_float2(alpha * ctx.acc[mf][j][0], alpha * ctx.acc[mf][j][1]);
                float2 v1 = make_float2(alpha * ctx.acc[mf][j][2], alpha * ctx.acc[mf][j][3]);
                *reinterpret_cast<float2*>(C + m0 * 2048 + n)       = v0;
                *reinterpret_cast<float2*>(C + (m0 + 8) * 2048 + n) = v1;
            } else {
                unsigned short* C = (unsigned short*)Ch + (long)blockIdx.z * sC;
                ushort2 v0 = make_ushort2(h1(ctx.acc[mf][j][0]), h1(ctx.acc[mf][j][1]));
                ushort2 v1 = make_ushort2(h1(ctx.acc[mf][j][2]), h1(ctx.acc[mf][j][3]));
                *reinterpret_cast<ushort2*>(C + m0 * 2048 + n)       = v0;
                *reinterpret_cast<ushort2*>(C + (m0 + 8) * 2048 + n) = v1;
            }
        }
    }
}

// ---------------------------------------------------------------------------
// Merged Q/K/V projection kernel: grid.z = weight index (0=Q, 1=K, 2=V).
// z=0 -> Qs, z=1 -> Ks (row-major), z=2 -> V^T scatter [b][n][s].
// ---------------------------------------------------------------------------
__global__ void __launch_bounds__(GTHR, 1)
gemm_qkv(const __half* __restrict__ xs, const __half* __restrict__ Wt,
         __half* __restrict__ Qs, __half* __restrict__ Ks,
         __half* __restrict__ Vt)
{
    extern __shared__ char smem[];
    const uint32_t sb = s2u(smem);
    const int tid  = threadIdx.x;
    const int warp = tid >> 5;
    const int lane = tid & 31;
    const int wm   = warp & 3;
    const int wn   = warp >> 2;
    const int z    = blockIdx.z;

    const long rowA0 = (long)blockIdx.y * 128;
    const long colB0 = (long)blockIdx.x * 128;

    MmaCtx ctx;
    gemm_mainloop(ctx, sb, tid, wm, wn, lane,
                  xs, Wt + (long)z * (long)WELEMS, rowA0, colB0);

    const int er = lane >> 2;
    const int ec = (lane & 3) << 1;
    if (z < 2) {
        unsigned short* C = (unsigned short*)(z == 0 ? Qs : Ks);
        #pragma unroll
        for (int mf = 0; mf < 2; mf++) {
            const long m0 = rowA0 + wm * 32 + mf * 16 + er;
            #pragma unroll
            for (int j = 0; j < 4; j++) {
                const long n = colB0 + wn * 32 + j * 8 + ec;
                ushort2 v0 = make_ushort2(h1(ctx.acc[mf][j][0]), h1(ctx.acc[mf][j][1]));
                ushort2 v1 = make_ushort2(h1(ctx.acc[mf][j][2]), h1(ctx.acc[mf][j][3]));
                *reinterpret_cast<ushort2*>(C + m0 * 2048 + n)       = v0;
                *reinterpret_cast<ushort2*>(C + (m0 + 8) * 2048 + n) = v1;
            }
        }
    } else {
        // V^T scatter: element (m, n) -> [b][n][s], b = m>>11, s = m&2047
        unsigned short* C = (unsigned short*)Vt;
        #pragma unroll
        for (int mf = 0; mf < 2; mf++) {
            const long m0 = rowA0 + wm * 32 + mf * 16 + er;
            #pragma unroll
            for (int j = 0; j < 4; j++) {
                const long n = colB0 + wn * 32 + j * 8 + ec;
                #pragma unroll
                for (int c = 0; c < 4; c++) {
                    long m = m0 + (c >> 1) * 8;
                    long nn = n + (c & 1);
                    long b = m >> 11, sl = m & 2047;
                    C[b * 4194304 + nn * 2048 + sl] = h1(ctx.acc[mf][j][c]);
                }
            }
        }
    }
}

// ---------------------------------------------------------------------------
// Merged conversion kernel:
//   blocks [0, 8192):      x fp32 -> fp16 (1024 elems per block)
//   blocks [8192, 24576):  W transposes, 32x32 tiles; weight = (bid-8192)/4096
// ---------------------------------------------------------------------------
__global__ void __launch_bounds__(256)
convall_kernel(const float* __restrict__ x,
               const float* __restrict__ Wq, const float* __restrict__ Wk,
               const float* __restrict__ Wv, const float* __restrict__ Wo,
               __half* __restrict__ xs, __half* __restrict__ Wt)
{
    const int bid = blockIdx.x;
    if (bid < 8192) {
        size_t i = ((size_t)bid * 256 + threadIdx.x) * 4;
        float4 v = *reinterpret_cast<const float4*>(x + i);
        ushort4 H;
        H.x = h1(v.x); H.y = h1(v.y); H.z = h1(v.z); H.w = h1(v.w);
        *reinterpret_cast<ushort4*>((unsigned short*)xs + i) = H;
        return;
    }
    const int t = bid - 8192;
    const int w = t >> 12;               // weight index 0..3
    const int ti = t & 4095;             // tile index within weight
    const float* W = (w == 0) ? Wq : (w == 1) ? Wk : (w == 2) ? Wv : Wo;
    __half* T = Wt + (size_t)w * WELEMS;

    __shared__ float tt[32][33];
    const int bx = (ti & 63) * 32, by = (ti >> 6) * 32;
    const int tx = threadIdx.x & 31, ty = threadIdx.x >> 5;   // 32 x 8
    #pragma unroll
    for (int rr = 0; rr < 4; rr++)
        tt[ty + 8 * rr][tx] = W[(size_t)(by + ty + 8 * rr) * 2048 + bx + tx];
    __syncthreads();
    #pragma unroll
    for (int rr = 0; rr < 4; rr++) {
        size_t o = (size_t)(bx + ty + 8 * rr) * 2048 + by + tx;
        ((unsigned short*)T)[o] = h1(tt[tx][ty + 8 * rr]);
    }
}

// ---------------------------------------------------------------------------
// Row softmax (fp32 in) -> P fp16. One block per row of 2048.
// ---------------------------------------------------------------------------
__global__ void __launch_bounds__(256)
softmax_kernel(const float* __restrict__ S, __half* __restrict__ P)
{
    const float4* row = reinterpret_cast<const float4*>(S + (size_t)blockIdx.x * SEQ);
    const int tid = threadIdx.x, lane = tid & 31, wid = tid >> 5;

    float4 a = row[tid];
    float4 b = row[tid + 256];

    float m = fmaxf(fmaxf(fmaxf(a.x, a.y), fmaxf(a.z, a.w)),
                    fmaxf(fmaxf(b.x, b.y), fmaxf(b.z, b.w)));
    #pragma unroll
    for (int o = 16; o > 0; o >>= 1) m = fmaxf(m, __shfl_xor_sync(~0u, m, o));

    __shared__ float redm[8], reds[8];
    if (lane == 0) redm[wid] = m;
    __syncthreads();
    float bm = fmaxf(fmaxf(fmaxf(redm[0], redm[1]), fmaxf(redm[2], redm[3])),
                     fmaxf(fmaxf(redm[4], redm[5]), fmaxf(redm[6], redm[7])));

    a.x = expf(a.x - bm); a.y = expf(a.y - bm); a.z = expf(a.z - bm); a.w = expf(a.w - bm);
    b.x = expf(b.x - bm); b.y = expf(b.y - bm); b.z = expf(b.z - bm); b.w = expf(b.w - bm);

    float sm = a.x + a.y + a.z + a.w + b.x + b.y + b.z + b.w;
    #pragma unroll
    for (int o = 16; o > 0; o >>= 1) sm += __shfl_xor_sync(~0u, sm, o);
    if (lane == 0) reds[wid] = sm;
    __syncthreads();
    float bs = reds[0] + reds[1] + reds[2] + reds[3] + reds[4] + reds[5] + reds[6] + reds[7];
    float inv = 1.0f / bs;

    const size_t base = (size_t)blockIdx.x * SEQ;
    unsigned short* PP = (unsigned short*)P;
    ushort4 H;
    H.x = h1(a.x * inv); H.y = h1(a.y * inv);
    H.z = h1(a.z * inv); H.w = h1(a.w * inv);
    *reinterpret_cast<ushort4*>(PP + base + tid * 4) = H;
    H.x = h1(b.x * inv); H.y = h1(b.y * inv);
    H.z = h1(b.z * inv); H.w = h1(b.w * inv);
    *reinterpret_cast<ushort4*>(PP + base + (tid + 256) * 4) = H;
}

// ---------------------------------------------------------------------------
// Launch
// ---------------------------------------------------------------------------
extern "C" void kernel_launch(void* const* d_in, const int* in_sizes, int n_in,
                              void* d_out, int out_size)
{
    (void)in_sizes; (void)n_in; (void)out_size;
    const float* x  = (const float*)d_in[0];
    const float* Wq = (const float*)d_in[1];
    const float* Wk = (const float*)d_in[2];
    const float* Wv = (const float*)d_in[3];
    const float* Wo = (const float*)d_in[4];
    float* out = (float*)d_out;

    __half *xs, *Wt, *Qs, *Ks, *Vt, *Ps, *Os;
    float* S;
    cudaGetSymbolAddress((void**)&xs, g_xs);
    cudaGetSymbolAddress((void**)&Wt, g_Wt);
    cudaGetSymbolAddress((void**)&Qs, g_Qs);
    cudaGetSymbolAddress((void**)&Ks, g_Ks);
    cudaGetSymbolAddress((void**)&Vt, g_Vt);
    cudaGetSymbolAddress((void**)&S,  g_S);
    cudaGetSymbolAddress((void**)&Ps, g_Ps);
    cudaGetSymbolAddress((void**)&Os, g_Os);

    cudaFuncSetAttribute(gemm_mma<0>, cudaFuncAttributeMaxDynamicSharedMemorySize, SMEM_SZ);
    cudaFuncSetAttribute(gemm_mma<2>, cudaFuncAttributeMaxDynamicSharedMemorySize, SMEM_SZ);
    cudaFuncSetAttribute(gemm_qkv,    cudaFuncAttributeMaxDynamicSharedMemorySize, SMEM_SZ);

    const float scale = 1.0f / sqrtf((float)D_MODEL);
    const long sBSS = (long)SEQ * SEQ;          // 4194304
    const long sSD  = (long)SEQ * D_MODEL;      // 4194304

    // all conversions in one launch (x conv + 4 weight transposes)
    convall_kernel<<<24576, 256>>>(x, Wq, Wk, Wv, Wo, xs, Wt);

    const dim3 gQKV(D_MODEL / 128, MROWS / 128, 3);    // (16, 32, 3) = 1536 CTAs
    const dim3 gProj(D_MODEL / 128, MROWS / 128, 1);   // (16, 32) = 512
    const dim3 gAttn(SEQ / 128, SEQ / 128, BATCH);     // (16, 16, 2) = 512

    // Q, K, V projections in one launch
    gemm_qkv<<<gQKV, GTHR, SMEM_SZ>>>(xs, Wt, Qs, Ks, Vt);
    // scores = scale * Q @ K^T  (fp32 epilogue)
    gemm_mma<0><<<gAttn, GTHR, SMEM_SZ>>>(Qs, Ks,
                                          S, nullptr, sSD, sSD, sBSS, scale);
    // softmax -> P fp16
    softmax_kernel<<<BATCH * SEQ, 256>>>(S, Ps);
    // O = P @ V  (B operand = V^T)
    gemm_mma<2><<<gAttn, GTHR, SMEM_SZ>>>(Ps, Vt,
                                          nullptr, Os, sBSS, sSD, sSD, 1.0f);
    // out = O @ W_o  (fp32 epilogue)
    gemm_mma<0><<<gProj, GTHR, SMEM_SZ>>>(Os, Wt + 3 * WELEMS,
                                          out, nullptr, 0, 0, 0, 1.0f);
}

// round 12
// speedup vs baseline: 1.1096x; 1.0828x over previous
#include <cuda_runtime.h>
#include <cuda_fp16.h>
#include <math.h>
#include <stdint.h>

#define D_MODEL 2048
#define BATCH   2
#define SEQ     2048
#define MROWS   (BATCH * SEQ)                 // 4096
#define ELEMS   ((size_t)MROWS * D_MODEL)     // 8388608
#define WELEMS  ((size_t)D_MODEL * D_MODEL)   // 4194304

// ---------------------------------------------------------------------------
// Device scratch (allocation-free contract) — all single fp16
// ---------------------------------------------------------------------------
__device__ __half g_xs[ELEMS];                      // x fp16
__device__ __half g_Wh[4 * WELEMS];                 // W fp16, [k][n] (as given)
__device__ __half g_Qs[ELEMS];                      // Q row-major
__device__ __half g_Ks[ELEMS];                      // K row-major
__device__ __half g_Vs[ELEMS];                      // V row-major [b][s][d]
__device__ float  g_S [(size_t)BATCH * SEQ * SEQ];  // scores fp32
__device__ __half g_Ps[(size_t)BATCH * SEQ * SEQ];  // softmax(P)
__device__ __half g_Os[ELEMS];                      // attn output

// ---------------------------------------------------------------------------
// Helpers
// ---------------------------------------------------------------------------
__device__ __forceinline__ uint32_t s2u(const void* p) {
    return (uint32_t)__cvta_generic_to_shared(p);
}
__device__ __forceinline__ void cp16(uint32_t dst, const void* src) {
    asm volatile("cp.async.cg.shared.global [%0], [%1], 16;\n"
                 :: "r"(dst), "l"(__cvta_generic_to_global(src)));
}
__device__ __forceinline__ void cp_commit() { asm volatile("cp.async.commit_group;"); }
template<int N> __device__ __forceinline__ void cp_wait() {
    asm volatile("cp.async.wait_group %0;" :: "n"(N));
}
__device__ __forceinline__ void ldm_x4(uint32_t* r, uint32_t addr) {
    asm volatile("ldmatrix.sync.aligned.m8n8.x4.shared.b16 {%0,%1,%2,%3}, [%4];"
                 : "=r"(r[0]), "=r"(r[1]), "=r"(r[2]), "=r"(r[3]) : "r"(addr));
}
__device__ __forceinline__ void ldm_x4_t(uint32_t* r, uint32_t addr) {
    asm volatile("ldmatrix.sync.aligned.m8n8.x4.trans.shared.b16 {%0,%1,%2,%3}, [%4];"
                 : "=r"(r[0]), "=r"(r[1]), "=r"(r[2]), "=r"(r[3]) : "r"(addr));
}
__device__ __forceinline__ void mma_f16(float* d, const uint32_t* a,
                                        uint32_t b0, uint32_t b1) {
    asm volatile(
        "mma.sync.aligned.m16n8k16.row.col.f32.f16.f16.f32 "
        "{%0,%1,%2,%3}, {%4,%5,%6,%7}, {%8,%9}, {%0,%1,%2,%3};"
        : "+f"(d[0]), "+f"(d[1]), "+f"(d[2]), "+f"(d[3])
        : "r"(a[0]), "r"(a[1]), "r"(a[2]), "r"(a[3]), "r"(b0), "r"(b1));
}
__device__ __forceinline__ unsigned short h1(float v) {
    __half hh = __float2half_rn(v);
    return *reinterpret_cast<unsigned short*>(&hh);
}

// ---------------------------------------------------------------------------
// Tiling (identical to R8 except optional N-major B path):
// CTA tile 128x128, 512 threads = 16 warps (4x4), warp tile 32x32,
// K-chunk 32, 4-stage cp.async, 1 CTA/SM.
// A smem: 128 rows x (64B data + 16B pad = 80B).
// B smem TRANSB=0 (K-major, rows=n): same as A.
// B smem TRANSB=1 (N-major [k][n], rows=k): 32 rows x (256B + 16B pad = 272B).
// 272/4 mod 32 = 4 -> 8 consecutive rows hit distinct bank groups: conflict-free.
// ---------------------------------------------------------------------------
#define KC      32
#define STAGES  4
#define ROWA    80
#define TILE_A  (128 * ROWA)        // 10240
#define ROWBT   272
#define TILE_BT (KC * ROWBT)        // 8704
#define STG0    (TILE_A + TILE_A)   // 20480  (TRANSB=0 stage)
#define STG1    (TILE_A + TILE_BT)  // 18944  (TRANSB=1 stage)
#define NCH     (2048 / KC)         // 64
#define SMEM_SZ (STAGES * STG0)     // 81920 (max of both)
#define GTHR    512

struct MmaCtx {
    float acc[2][4][4];
};

template<int TRANSB>
__device__ __forceinline__ void gemm_mainloop(
    MmaCtx& ctx, uint32_t sb, int tid, int wm, int wn, int lane,
    const __half* A0, const __half* B0, long rowA0, long colB0)
{
    const int STG = TRANSB ? STG1 : STG0;

    // A loads: 128 rows x 4 segs, 1 cp16/thread
    const int lrA = tid >> 2;
    const int lsA = tid & 3;
    // B loads TRANSB=0: same pattern as A (rows = n)
    // B loads TRANSB=1: 32 k-rows x 16 segs, 1 cp16/thread
    const int lrB = TRANSB ? (tid >> 4) : (tid >> 2);
    const int lsB = TRANSB ? (tid & 15) : (tid & 3);

    auto load_chunk = [&](int chunk, int stage) {
        const int k0 = chunk * KC;
        const uint32_t base = sb + (uint32_t)stage * STG;
        cp16(base + (uint32_t)(lrA * ROWA + lsA * 16),
             A0 + (rowA0 + lrA) * 2048 + k0 + lsA * 8);
        if (TRANSB) {
            // global row = k0+lrB, cols colB0 + lsB*8 (16B)
            cp16(base + TILE_A + (uint32_t)(lrB * ROWBT + lsB * 16),
                 B0 + (long)(k0 + lrB) * 2048 + colB0 + lsB * 8);
        } else {
            cp16(base + TILE_A + (uint32_t)(lrB * ROWA + lsB * 16),
                 B0 + (colB0 + lrB) * 2048 + k0 + lsB * 8);
        }
    };

    const int fr  = lane & 15;
    const int fc  = (lane >> 4) << 4;
    const uint32_t aoff = (uint32_t)((wm * 32 + fr) * ROWA + fc);
    // TRANSB=0 ldmatrix (rows = n)
    const uint32_t boff0 = (uint32_t)((wn * 32 + fr) * ROWA + fc);
    // TRANSB=1 trans-ldmatrix (rows = k): lane -> k row + n byte
    const int kr   = (lane & 7) + ((lane >> 4) << 3);
    const int nby  = ((lane >> 3) & 1) << 4;
    const uint32_t boff1 = (uint32_t)(kr * ROWBT + wn * 64 + nby);

    #pragma unroll
    for (int i = 0; i < 2; i++)
        #pragma unroll
        for (int j = 0; j < 4; j++)
            #pragma unroll
            for (int c = 0; c < 4; c++)
                ctx.acc[i][j][c] = 0.0f;

    load_chunk(0, 0); cp_commit();
    load_chunk(1, 1); cp_commit();
    load_chunk(2, 2); cp_commit();

    for (int i = 0; i < NCH; i++) {
        if (i < NCH - 2)       cp_wait<2>();
        else if (i == NCH - 2) cp_wait<1>();
        else                   cp_wait<0>();
        __syncthreads();

        if (i + STAGES - 1 < NCH) {
            load_chunk(i + STAGES - 1, (i + STAGES - 1) & (STAGES - 1));
            cp_commit();
        }

        const uint32_t base = sb + (uint32_t)(i & (STAGES - 1)) * STG;
        #pragma unroll
        for (int ks = 0; ks < 2; ks++) {
            uint32_t aa[2][4], bb[2][4];
            #pragma unroll
            for (int mf = 0; mf < 2; mf++) {
                uint32_t ad = base + aoff + (uint32_t)(mf * 16 * ROWA + ks * 32);
                ldm_x4(aa[mf], ad);
            }
            #pragma unroll
            for (int nf = 0; nf < 2; nf++) {
                if (TRANSB) {
                    uint32_t bd = base + TILE_A + boff1
                                + (uint32_t)(ks * 16 * ROWBT + nf * 32);
                    ldm_x4_t(bb[nf], bd);
                } else {
                    uint32_t bd = base + TILE_A + boff0
                                + (uint32_t)(nf * 16 * ROWA + ks * 32);
                    ldm_x4(bb[nf], bd);
                }
            }
            #pragma unroll
            for (int mf = 0; mf < 2; mf++)
                #pragma unroll
                for (int j = 0; j < 4; j++) {
                    const int nf = j >> 1, o = j & 1;
                    mma_f16(ctx.acc[mf][j], aa[mf], bb[nf][o], bb[nf][o + 2]);
                }
        }
    }
    __syncthreads();
}

// ---------------------------------------------------------------------------
// Generic GEMM kernel (EPI: 0 = fp32*alpha -> Cf ; 2 = fp16 -> Ch)
// ---------------------------------------------------------------------------
template<int EPI, int TRANSB>
__global__ void __launch_bounds__(GTHR, 1)
gemm_mma(const __half* __restrict__ A, const __half* __restrict__ B,
         float* __restrict__ Cf, __half* __restrict__ Ch,
         long sA, long sB, long sC, float alpha)
{
    extern __shared__ char smem[];
    const uint32_t sb = s2u(smem);
    const int tid  = threadIdx.x;
    const int warp = tid >> 5;
    const int lane = tid & 31;
    const int wm   = warp & 3;
    const int wn   = warp >> 2;

    const long rowA0 = (long)blockIdx.y * 128;
    const long colB0 = (long)blockIdx.x * 128;

    MmaCtx ctx;
    gemm_mainloop<TRANSB>(ctx, sb, tid, wm, wn, lane,
                          A + (long)blockIdx.z * sA, B + (long)blockIdx.z * sB,
                          rowA0, colB0);

    const int er = lane >> 2;
    const int ec = (lane & 3) << 1;
    #pragma unroll
    for (int mf = 0; mf < 2; mf++) {
        const long m0 = rowA0 + wm * 32 + mf * 16 + er;
        #pragma unroll
        for (int j = 0; j < 4; j++) {
            const long n = colB0 + wn * 32 + j * 8 + ec;
            if (EPI == 0) {
                float* C = Cf + (long)blockIdx.z * sC;
                float2 v0 = make_float2(alpha * ctx.acc[mf][j][0], alpha * ctx.acc[mf][j][1]);
                float2 v1 = make_float2(alpha * ctx.acc[mf][j][2], alpha * ctx.acc[mf][j][3]);
                *reinterpret_cast<float2*>(C + m0 * 2048 + n)       = v0;
                *reinterpret_cast<float2*>(C + (m0 + 8) * 2048 + n) = v1;
            } else {
                unsigned short* C = (unsigned short*)Ch + (long)blockIdx.z * sC;
                ushort2 v0 = make_ushort2(h1(ctx.acc[mf][j][0]), h1(ctx.acc[mf][j][1]));
                ushort2 v1 = make_ushort2(h1(ctx.acc[mf][j][2]), h1(ctx.acc[mf][j][3]));
                *reinterpret_cast<ushort2*>(C + m0 * 2048 + n)       = v0;
                *reinterpret_cast<ushort2*>(C + (m0 + 8) * 2048 + n) = v1;
            }
        }
    }
}

// ---------------------------------------------------------------------------
// Merged Q/K/V projection kernel: grid.z = weight index (0=Q, 1=K, 2=V).
// B = W[z] in [k][n] layout (TRANSB=1). All outputs row-major fp16.
// ---------------------------------------------------------------------------
__global__ void __launch_bounds__(GTHR, 1)
gemm_qkv(const __half* __restrict__ xs, const __half* __restrict__ Wh,
         __half* __restrict__ Qs, __half* __restrict__ Ks,
         __half* __restrict__ Vs)
{
    extern __shared__ char smem[];
    const uint32_t sb = s2u(smem);
    const int tid  = threadIdx.x;
    const int warp = tid >> 5;
    const int lane = tid & 31;
    const int wm   = warp & 3;
    const int wn   = warp >> 2;
    const int z    = blockIdx.z;

    const long rowA0 = (long)blockIdx.y * 128;
    const long colB0 = (long)blockIdx.x * 128;

    MmaCtx ctx;
    gemm_mainloop<1>(ctx, sb, tid, wm, wn, lane,
                     xs, Wh + (long)z * (long)WELEMS, rowA0, colB0);

    unsigned short* C = (unsigned short*)(z == 0 ? Qs : (z == 1 ? Ks : Vs));
    const int er = lane >> 2;
    const int ec = (lane & 3) << 1;
    #pragma unroll
    for (int mf = 0; mf < 2; mf++) {
        const long m0 = rowA0 + wm * 32 + mf * 16 + er;
        #pragma unroll
        for (int j = 0; j < 4; j++) {
            const long n = colB0 + wn * 32 + j * 8 + ec;
            ushort2 v0 = make_ushort2(h1(ctx.acc[mf][j][0]), h1(ctx.acc[mf][j][1]));
            ushort2 v1 = make_ushort2(h1(ctx.acc[mf][j][2]), h1(ctx.acc[mf][j][3]));
            *reinterpret_cast<ushort2*>(C + m0 * 2048 + n)       = v0;
            *reinterpret_cast<ushort2*>(C + (m0 + 8) * 2048 + n) = v1;
        }
    }
}

// ---------------------------------------------------------------------------
// Merged conversion kernel (all elementwise, coalesced):
//   blocks [0, 8192):      x fp32 -> fp16
//   blocks [8192, 24576):  W fp32 -> fp16 (same [k][n] layout, no transpose)
// ---------------------------------------------------------------------------
__global__ void __launch_bounds__(256)
convall_kernel(const float* __restrict__ x,
               const float* __restrict__ Wq, const float* __restrict__ Wk,
               const float* __restrict__ Wv, const float* __restrict__ Wo,
               __half* __restrict__ xs, __half* __restrict__ Wh)
{
    const int bid = blockIdx.x;
    const float* src;
    unsigned short* dst;
    size_t i;
    if (bid < 8192) {
        src = x; dst = (unsigned short*)xs;
        i = ((size_t)bid * 256 + threadIdx.x) * 4;
    } else {
        const int t = bid - 8192;
        const int w = t >> 12;           // weight index 0..3
        src = (w == 0) ? Wq : (w == 1) ? Wk : (w == 2) ? Wv : Wo;
        dst = (unsigned short*)(Wh + (size_t)w * WELEMS);
        i = ((size_t)(t & 4095) * 256 + threadIdx.x) * 4;
    }
    float4 v = *reinterpret_cast<const float4*>(src + i);
    ushort4 H;
    H.x = h1(v.x); H.y = h1(v.y); H.z = h1(v.z); H.w = h1(v.w);
    *reinterpret_cast<ushort4*>(dst + i) = H;
}

// ---------------------------------------------------------------------------
// Row softmax (fp32 in) -> P fp16. One block per row of 2048.
// ---------------------------------------------------------------------------
__global__ void __launch_bounds__(256)
softmax_kernel(const float* __restrict__ S, __half* __restrict__ P)
{
    const float4* row = reinterpret_cast<const float4*>(S + (size_t)blockIdx.x * SEQ);
    const int tid = threadIdx.x, lane = tid & 31, wid = tid >> 5;

    float4 a = row[tid];
    float4 b = row[tid + 256];

    float m = fmaxf(fmaxf(fmaxf(a.x, a.y), fmaxf(a.z, a.w)),
                    fmaxf(fmaxf(b.x, b.y), fmaxf(b.z, b.w)));
    #pragma unroll
    for (int o = 16; o > 0; o >>= 1) m = fmaxf(m, __shfl_xor_sync(~0u, m, o));

    __shared__ float redm[8], reds[8];
    if (lane == 0) redm[wid] = m;
    __syncthreads();
    float bm = fmaxf(fmaxf(fmaxf(redm[0], redm[1]), fmaxf(redm[2], redm[3])),
                     fmaxf(fmaxf(redm[4], redm[5]), fmaxf(redm[6], redm[7])));

    a.x = expf(a.x - bm); a.y = expf(a.y - bm); a.z = expf(a.z - bm); a.w = expf(a.w - bm);
    b.x = expf(b.x - bm); b.y = expf(b.y - bm); b.z = expf(b.z - bm); b.w = expf(b.w - bm);

    float sm = a.x + a.y + a.z + a.w + b.x + b.y + b.z + b.w;
    #pragma unroll
    for (int o = 16; o > 0; o >>= 1) sm += __shfl_xor_sync(~0u, sm, o);
    if (lane == 0) reds[wid] = sm;
    __syncthreads();
    float bs = reds[0] + reds[1] + reds[2] + reds[3] + reds[4] + reds[5] + reds[6] + reds[7];
    float inv = 1.0f / bs;

    const size_t base = (size_t)blockIdx.x * SEQ;
    unsigned short* PP = (unsigned short*)P;
    ushort4 H;
    H.x = h1(a.x * inv); H.y = h1(a.y * inv);
    H.z = h1(a.z * inv); H.w = h1(a.w * inv);
    *reinterpret_cast<ushort4*>(PP + base + tid * 4) = H;
    H.x = h1(b.x * inv); H.y = h1(b.y * inv);
    H.z = h1(b.z * inv); H.w = h1(b.w * inv);
    *reinterpret_cast<ushort4*>(PP + base + (tid + 256) * 4) = H;
}

// ---------------------------------------------------------------------------
// Launch
// ---------------------------------------------------------------------------
extern "C" void kernel_launch(void* const* d_in, const int* in_sizes, int n_in,
                              void* d_out, int out_size)
{
    (void)in_sizes; (void)n_in; (void)out_size;
    const float* x  = (const float*)d_in[0];
    const float* Wq = (const float*)d_in[1];
    const float* Wk = (const float*)d_in[2];
    const float* Wv = (const float*)d_in[3];
    const float* Wo = (const float*)d_in[4];
    float* out = (float*)d_out;

    __half *xs, *Wh, *Qs, *Ks, *Vs, *Ps, *Os;
    float* S;
    cudaGetSymbolAddress((void**)&xs, g_xs);
    cudaGetSymbolAddress((void**)&Wh, g_Wh);
    cudaGetSymbolAddress((void**)&Qs, g_Qs);
    cudaGetSymbolAddress((void**)&Ks, g_Ks);
    cudaGetSymbolAddress((void**)&Vs, g_Vs);
    cudaGetSymbolAddress((void**)&S,  g_S);
    cudaGetSymbolAddress((void**)&Ps, g_Ps);
    cudaGetSymbolAddress((void**)&Os, g_Os);

    cudaFuncSetAttribute(gemm_mma<0,0>, cudaFuncAttributeMaxDynamicSharedMemorySize, SMEM_SZ);
    cudaFuncSetAttribute(gemm_mma<2,1>, cudaFuncAttributeMaxDynamicSharedMemorySize, SMEM_SZ);
    cudaFuncSetAttribute(gemm_mma<0,1>, cudaFuncAttributeMaxDynamicSharedMemorySize, SMEM_SZ);
    cudaFuncSetAttribute(gemm_qkv,      cudaFuncAttributeMaxDynamicSharedMemorySize, SMEM_SZ);

    const float scale = 1.0f / sqrtf((float)D_MODEL);
    const long sBSS = (long)SEQ * SEQ;          // 4194304
    const long sSD  = (long)SEQ * D_MODEL;      // 4194304

    // all conversions in one launch (x + 4 weights, elementwise fp32->fp16)
    convall_kernel<<<24576, 256>>>(x, Wq, Wk, Wv, Wo, xs, Wh);

    const dim3 gQKV(D_MODEL / 128, MROWS / 128, 3);    // (16, 32, 3) = 1536 CTAs
    const dim3 gProj(D_MODEL / 128, MROWS / 128, 1);   // (16, 32) = 512
    const dim3 gAttn(SEQ / 128, SEQ / 128, BATCH);     // (16, 16, 2) = 512

    // Q, K, V projections in one launch (B = W [k][n], trans path)
    gemm_qkv<<<gQKV, GTHR, SMEM_SZ>>>(xs, Wh, Qs, Ks, Vs);
    // scores = scale * Q @ K^T  (K is [n][k] K-major: non-trans path)
    gemm_mma<0,0><<<gAttn, GTHR, SMEM_SZ>>>(Qs, Ks,
                                            S, nullptr, sSD, sSD, sBSS, scale);
    // softmax -> P fp16
    softmax_kernel<<<BATCH * SEQ, 256>>>(S, Ps);
    // O = P @ V  (V is [s][d] = [k][n]: trans path)
    gemm_mma<2,1><<<gAttn, GTHR, SMEM_SZ>>>(Ps, Vs,
                                            nullptr, Os, sBSS, sSD, sSD, 1.0f);
    // out = O @ W_o  (Wo is [k][n]: trans path)
    gemm_mma<0,1><<<gProj, GTHR, SMEM_SZ>>>(Os, Wh + 3 * WELEMS,
                                            out, nullptr, 0, 0, 0, 1.0f);
}

// round 13
// speedup vs baseline: 1.1515x; 1.0377x over previous
#include <cuda_runtime.h>
#include <cuda_fp16.h>
#include <math.h>
#include <stdint.h>

#define D_MODEL 2048
#define BATCH   2
#define SEQ     2048
#define MROWS   (BATCH * SEQ)                 // 4096
#define ELEMS   ((size_t)MROWS * D_MODEL)     // 8388608
#define WELEMS  ((size_t)D_MODEL * D_MODEL)   // 4194304

// ---------------------------------------------------------------------------
// Device scratch (allocation-free contract) — all single fp16
// ---------------------------------------------------------------------------
__device__ __half g_xs[ELEMS];                      // x fp16
__device__ __half g_Wh[4 * WELEMS];                 // W fp16, [k][n] (as given)
__device__ __half g_Qs[ELEMS];                      // Q row-major
__device__ __half g_Ks[ELEMS];                      // K row-major
__device__ __half g_Vs[ELEMS];                      // V row-major [b][s][d]
__device__ float  g_S [(size_t)BATCH * SEQ * SEQ];  // scores fp32
__device__ __half g_Ps[(size_t)BATCH * SEQ * SEQ];  // softmax(P)
__device__ __half g_VW[ELEMS];                      // V @ Wo, [b][s][d]

// ---------------------------------------------------------------------------
// Helpers
// ---------------------------------------------------------------------------
__device__ __forceinline__ uint32_t s2u(const void* p) {
    return (uint32_t)__cvta_generic_to_shared(p);
}
__device__ __forceinline__ void cp16(uint32_t dst, const void* src) {
    asm volatile("cp.async.cg.shared.global [%0], [%1], 16;\n"
                 :: "r"(dst), "l"(__cvta_generic_to_global(src)));
}
__device__ __forceinline__ void cp_commit() { asm volatile("cp.async.commit_group;"); }
template<int N> __device__ __forceinline__ void cp_wait() {
    asm volatile("cp.async.wait_group %0;" :: "n"(N));
}
__device__ __forceinline__ void ldm_x4(uint32_t* r, uint32_t addr) {
    asm volatile("ldmatrix.sync.aligned.m8n8.x4.shared.b16 {%0,%1,%2,%3}, [%4];"
                 : "=r"(r[0]), "=r"(r[1]), "=r"(r[2]), "=r"(r[3]) : "r"(addr));
}
__device__ __forceinline__ void ldm_x4_t(uint32_t* r, uint32_t addr) {
    asm volatile("ldmatrix.sync.aligned.m8n8.x4.trans.shared.b16 {%0,%1,%2,%3}, [%4];"
                 : "=r"(r[0]), "=r"(r[1]), "=r"(r[2]), "=r"(r[3]) : "r"(addr));
}
__device__ __forceinline__ void mma_f16(float* d, const uint32_t* a,
                                        uint32_t b0, uint32_t b1) {
    asm volatile(
        "mma.sync.aligned.m16n8k16.row.col.f32.f16.f16.f32 "
        "{%0,%1,%2,%3}, {%4,%5,%6,%7}, {%8,%9}, {%0,%1,%2,%3};"
        : "+f"(d[0]), "+f"(d[1]), "+f"(d[2]), "+f"(d[3])
        : "r"(a[0]), "r"(a[1]), "r"(a[2]), "r"(a[3]), "r"(b0), "r"(b1));
}
__device__ __forceinline__ unsigned short h1(float v) {
    __half hh = __float2half_rn(v);
    return *reinterpret_cast<unsigned short*>(&hh);
}

// ---------------------------------------------------------------------------
// Tiling (R12 mainloop, unchanged):
// CTA tile 128x128, 512 threads = 16 warps (4x4), warp tile 32x32,
// K-chunk 32, 4-stage cp.async, 1 CTA/SM.
// A smem: 128 rows x (64B data + 16B pad = 80B).
// B smem TRANSB=0 (K-major, rows=n): same as A.
// B smem TRANSB=1 (N-major [k][n], rows=k): 32 rows x (256B + 16B pad = 272B).
// ---------------------------------------------------------------------------
#define KC      32
#define STAGES  4
#define ROWA    80
#define TILE_A  (128 * ROWA)        // 10240
#define ROWBT   272
#define TILE_BT (KC * ROWBT)        // 8704
#define STG0    (TILE_A + TILE_A)   // 20480  (TRANSB=0 stage)
#define STG1    (TILE_A + TILE_BT)  // 18944  (TRANSB=1 stage)
#define NCH     (2048 / KC)         // 64
#define SMEM_SZ (STAGES * STG0)     // 81920 (max of both)
#define GTHR    512

struct MmaCtx {
    float acc[2][4][4];
};

template<int TRANSB>
__device__ __forceinline__ void gemm_mainloop(
    MmaCtx& ctx, uint32_t sb, int tid, int wm, int wn, int lane,
    const __half* A0, const __half* B0, long rowA0, long colB0)
{
    const int STG = TRANSB ? STG1 : STG0;

    const int lrA = tid >> 2;
    const int lsA = tid & 3;
    const int lrB = TRANSB ? (tid >> 4) : (tid >> 2);
    const int lsB = TRANSB ? (tid & 15) : (tid & 3);

    auto load_chunk = [&](int chunk, int stage) {
        const int k0 = chunk * KC;
        const uint32_t base = sb + (uint32_t)stage * STG;
        cp16(base + (uint32_t)(lrA * ROWA + lsA * 16),
             A0 + (rowA0 + lrA) * 2048 + k0 + lsA * 8);
        if (TRANSB) {
            cp16(base + TILE_A + (uint32_t)(lrB * ROWBT + lsB * 16),
                 B0 + (long)(k0 + lrB) * 2048 + colB0 + lsB * 8);
        } else {
            cp16(base + TILE_A + (uint32_t)(lrB * ROWA + lsB * 16),
                 B0 + (colB0 + lrB) * 2048 + k0 + lsB * 8);
        }
    };

    const int fr  = lane & 15;
    const int fc  = (lane >> 4) << 4;
    const uint32_t aoff = (uint32_t)((wm * 32 + fr) * ROWA + fc);
    const uint32_t boff0 = (uint32_t)((wn * 32 + fr) * ROWA + fc);
    const int kr   = (lane & 7) + ((lane >> 4) << 3);
    const int nby  = ((lane >> 3) & 1) << 4;
    const uint32_t boff1 = (uint32_t)(kr * ROWBT + wn * 64 + nby);

    #pragma unroll
    for (int i = 0; i < 2; i++)
        #pragma unroll
        for (int j = 0; j < 4; j++)
            #pragma unroll
            for (int c = 0; c < 4; c++)
                ctx.acc[i][j][c] = 0.0f;

    load_chunk(0, 0); cp_commit();
    load_chunk(1, 1); cp_commit();
    load_chunk(2, 2); cp_commit();

    for (int i = 0; i < NCH; i++) {
        if (i < NCH - 2)       cp_wait<2>();
        else if (i == NCH - 2) cp_wait<1>();
        else                   cp_wait<0>();
        __syncthreads();

        if (i + STAGES - 1 < NCH) {
            load_chunk(i + STAGES - 1, (i + STAGES - 1) & (STAGES - 1));
            cp_commit();
        }

        const uint32_t base = sb + (uint32_t)(i & (STAGES - 1)) * STG;
        #pragma unroll
        for (int ks = 0; ks < 2; ks++) {
            uint32_t aa[2][4], bb[2][4];
            #pragma unroll
            for (int mf = 0; mf < 2; mf++) {
                uint32_t ad = base + aoff + (uint32_t)(mf * 16 * ROWA + ks * 32);
                ldm_x4(aa[mf], ad);
            }
            #pragma unroll
            for (int nf = 0; nf < 2; nf++) {
                if (TRANSB) {
                    uint32_t bd = base + TILE_A + boff1
                                + (uint32_t)(ks * 16 * ROWBT + nf * 32);
                    ldm_x4_t(bb[nf], bd);
                } else {
                    uint32_t bd = base + TILE_A + boff0
                                + (uint32_t)(nf * 16 * ROWA + ks * 32);
                    ldm_x4(bb[nf], bd);
                }
            }
            #pragma unroll
            for (int mf = 0; mf < 2; mf++)
                #pragma unroll
                for (int j = 0; j < 4; j++) {
                    const int nf = j >> 1, o = j & 1;
                    mma_f16(ctx.acc[mf][j], aa[mf], bb[nf][o], bb[nf][o + 2]);
                }
        }
    }
    __syncthreads();
}

// ---------------------------------------------------------------------------
// Epilogue helpers
// ---------------------------------------------------------------------------
__device__ __forceinline__ void epi_f32(const MmaCtx& ctx, float* C,
                                        long rowA0, long colB0,
                                        int wm, int wn, int lane, float alpha)
{
    const int er = lane >> 2;
    const int ec = (lane & 3) << 1;
    #pragma unroll
    for (int mf = 0; mf < 2; mf++) {
        const long m0 = rowA0 + wm * 32 + mf * 16 + er;
        #pragma unroll
        for (int j = 0; j < 4; j++) {
            const long n = colB0 + wn * 32 + j * 8 + ec;
            float2 v0 = make_float2(alpha * ctx.acc[mf][j][0], alpha * ctx.acc[mf][j][1]);
            float2 v1 = make_float2(alpha * ctx.acc[mf][j][2], alpha * ctx.acc[mf][j][3]);
            *reinterpret_cast<float2*>(C + m0 * 2048 + n)       = v0;
            *reinterpret_cast<float2*>(C + (m0 + 8) * 2048 + n) = v1;
        }
    }
}

__device__ __forceinline__ void epi_f16(const MmaCtx& ctx, unsigned short* C,
                                        long rowA0, long colB0,
                                        int wm, int wn, int lane)
{
    const int er = lane >> 2;
    const int ec = (lane & 3) << 1;
    #pragma unroll
    for (int mf = 0; mf < 2; mf++) {
        const long m0 = rowA0 + wm * 32 + mf * 16 + er;
        #pragma unroll
        for (int j = 0; j < 4; j++) {
            const long n = colB0 + wn * 32 + j * 8 + ec;
            ushort2 v0 = make_ushort2(h1(ctx.acc[mf][j][0]), h1(ctx.acc[mf][j][1]));
            ushort2 v1 = make_ushort2(h1(ctx.acc[mf][j][2]), h1(ctx.acc[mf][j][3]));
            *reinterpret_cast<ushort2*>(C + m0 * 2048 + n)       = v0;
            *reinterpret_cast<ushort2*>(C + (m0 + 8) * 2048 + n) = v1;
        }
    }
}

// ---------------------------------------------------------------------------
// Generic GEMM kernel (EPI: 0 = fp32*alpha -> Cf ; 2 = fp16 -> Ch)
// ---------------------------------------------------------------------------
template<int EPI, int TRANSB>
__global__ void __launch_bounds__(GTHR, 1)
gemm_mma(const __half* __restrict__ A, const __half* __restrict__ B,
         float* __restrict__ Cf, __half* __restrict__ Ch,
         long sA, long sB, long sC, float alpha)
{
    extern __shared__ char smem[];
    const uint32_t sb = s2u(smem);
    const int tid  = threadIdx.x;
    const int warp = tid >> 5;
    const int lane = tid & 31;
    const int wm   = warp & 3;
    const int wn   = warp >> 2;

    const long rowA0 = (long)blockIdx.y * 128;
    const long colB0 = (long)blockIdx.x * 128;

    MmaCtx ctx;
    gemm_mainloop<TRANSB>(ctx, sb, tid, wm, wn, lane,
                          A + (long)blockIdx.z * sA, B + (long)blockIdx.z * sB,
                          rowA0, colB0);

    if (EPI == 0)
        epi_f32(ctx, Cf + (long)blockIdx.z * sC, rowA0, colB0, wm, wn, lane, alpha);
    else
        epi_f16(ctx, (unsigned short*)Ch + (long)blockIdx.z * sC,
                rowA0, colB0, wm, wn, lane);
}

// ---------------------------------------------------------------------------
// Merged Q/K/V projection kernel: grid.z = weight index (0=Q, 1=K, 2=V).
// ---------------------------------------------------------------------------
__global__ void __launch_bounds__(GTHR, 1)
gemm_qkv(const __half* __restrict__ xs, const __half* __restrict__ Wh,
         __half* __restrict__ Qs, __half* __restrict__ Ks,
         __half* __restrict__ Vs)
{
    extern __shared__ char smem[];
    const uint32_t sb = s2u(smem);
    const int tid  = threadIdx.x;
    const int warp = tid >> 5;
    const int lane = tid & 31;
    const int wm   = warp & 3;
    const int wn   = warp >> 2;
    const int z    = blockIdx.z;

    const long rowA0 = (long)blockIdx.y * 128;
    const long colB0 = (long)blockIdx.x * 128;

    MmaCtx ctx;
    gemm_mainloop<1>(ctx, sb, tid, wm, wn, lane,
                     xs, Wh + (long)z * (long)WELEMS, rowA0, colB0);

    unsigned short* C = (unsigned short*)(z == 0 ? Qs : (z == 1 ? Ks : Vs));
    epi_f16(ctx, C, rowA0, colB0, wm, wn, lane);
}

// ---------------------------------------------------------------------------
// Fused scores + V@Wo kernel, grid (16,16,4):
//   z=0,1: scores[z] = scale * Q[z] @ K[z]^T   (TRANSB=0, fp32 epi)
//   z=2,3: VW[z-2]   = V[z-2] @ Wo             (TRANSB=1, fp16 epi)
// One 1024-CTA launch = 6.92 waves -> tails merged.
// ---------------------------------------------------------------------------
__global__ void __launch_bounds__(GTHR, 1)
gemm_scores_vwo(const __half* __restrict__ Qs, const __half* __restrict__ Ks,
                const __half* __restrict__ Vs, const __half* __restrict__ Wo,
                float* __restrict__ S, __half* __restrict__ VW, float scale)
{
    extern __shared__ char smem[];
    const uint32_t sb = s2u(smem);
    const int tid  = threadIdx.x;
    const int warp = tid >> 5;
    const int lane = tid & 31;
    const int wm   = warp & 3;
    const int wn   = warp >> 2;
    const int z    = blockIdx.z;

    const long rowA0 = (long)blockIdx.y * 128;
    const long colB0 = (long)blockIdx.x * 128;
    const long sSD  = (long)SEQ * D_MODEL;
    const long sBSS = (long)SEQ * SEQ;

    MmaCtx ctx;
    if (z < 2) {
        gemm_mainloop<0>(ctx, sb, tid, wm, wn, lane,
                         Qs + z * sSD, Ks + z * sSD, rowA0, colB0);
        epi_f32(ctx, S + z * sBSS, rowA0, colB0, wm, wn, lane, scale);
    } else {
        gemm_mainloop<1>(ctx, sb, tid, wm, wn, lane,
                         Vs + (z - 2) * sSD, Wo, rowA0, colB0);
        epi_f16(ctx, (unsigned short*)VW + (z - 2) * sSD, rowA0, colB0, wm, wn, lane);
    }
}

// ---------------------------------------------------------------------------
// Merged conversion kernel (elementwise, coalesced):
//   blocks [0, 8192):      x fp32 -> fp16
//   blocks [8192, 24576):  W fp32 -> fp16
// ---------------------------------------------------------------------------
__global__ void __launch_bounds__(256)
convall_kernel(const float* __restrict__ x,
               const float* __restrict__ Wq, const float* __restrict__ Wk,
               const float* __restrict__ Wv, const float* __restrict__ Wo,
               __half* __restrict__ xs, __half* __restrict__ Wh)
{
    const int bid = blockIdx.x;
    const float* src;
    unsigned short* dst;
    size_t i;
    if (bid < 8192) {
        src = x; dst = (unsigned short*)xs;
        i = ((size_t)bid * 256 + threadIdx.x) * 4;
    } else {
        const int t = bid - 8192;
        const int w = t >> 12;
        src = (w == 0) ? Wq : (w == 1) ? Wk : (w == 2) ? Wv : Wo;
        dst = (unsigned short*)(Wh + (size_t)w * WELEMS);
        i = ((size_t)(t & 4095) * 256 + threadIdx.x) * 4;
    }
    float4 v = *reinterpret_cast<const float4*>(src + i);
    ushort4 H;
    H.x = h1(v.x); H.y = h1(v.y); H.z = h1(v.z); H.w = h1(v.w);
    *reinterpret_cast<ushort4*>(dst + i) = H;
}

// ---------------------------------------------------------------------------
// Row softmax (fp32 in) -> P fp16. One block per row of 2048.
// ---------------------------------------------------------------------------
__global__ void __launch_bounds__(256)
softmax_kernel(const float* __restrict__ S, __half* __restrict__ P)
{
    const float4* row = reinterpret_cast<const float4*>(S + (size_t)blockIdx.x * SEQ);
    const int tid = threadIdx.x, lane = tid & 31, wid = tid >> 5;

    float4 a = row[tid];
    float4 b = row[tid + 256];

    float m = fmaxf(fmaxf(fmaxf(a.x, a.y), fmaxf(a.z, a.w)),
                    fmaxf(fmaxf(b.x, b.y), fmaxf(b.z, b.w)));
    #pragma unroll
    for (int o = 16; o > 0; o >>= 1) m = fmaxf(m, __shfl_xor_sync(~0u, m, o));

    __shared__ float redm[8], reds[8];
    if (lane == 0) redm[wid] = m;
    __syncthreads();
    float bm = fmaxf(fmaxf(fmaxf(redm[0], redm[1]), fmaxf(redm[2], redm[3])),
                     fmaxf(fmaxf(redm[4], redm[5]), fmaxf(redm[6], redm[7])));

    a.x = expf(a.x - bm); a.y = expf(a.y - bm); a.z = expf(a.z - bm); a.w = expf(a.w - bm);
    b.x = expf(b.x - bm); b.y = expf(b.y - bm); b.z = expf(b.z - bm); b.w = expf(b.w - bm);

    float sm = a.x + a.y + a.z + a.w + b.x + b.y + b.z + b.w;
    #pragma unroll
    for (int o = 16; o > 0; o >>= 1) sm += __shfl_xor_sync(~0u, sm, o);
    if (lane == 0) reds[wid] = sm;
    __syncthreads();
    float bs = reds[0] + reds[1] + reds[2] + reds[3] + reds[4] + reds[5] + reds[6] + reds[7];
    float inv = 1.0f / bs;

    const size_t base = (size_t)blockIdx.x * SEQ;
    unsigned short* PP = (unsigned short*)P;
    ushort4 H;
    H.x = h1(a.x * inv); H.y = h1(a.y * inv);
    H.z = h1(a.z * inv); H.w = h1(a.w * inv);
    *reinterpret_cast<ushort4*>(PP + base + tid * 4) = H;
    H.x = h1(b.x * inv); H.y = h1(b.y * inv);
    H.z = h1(b.z * inv); H.w = h1(b.w * inv);
    *reinterpret_cast<ushort4*>(PP + base + (tid + 256) * 4) = H;
}

// ---------------------------------------------------------------------------
// Launch
// ---------------------------------------------------------------------------
extern "C" void kernel_launch(void* const* d_in, const int* in_sizes, int n_in,
                              void* d_out, int out_size)
{
    (void)in_sizes; (void)n_in; (void)out_size;
    const float* x  = (const float*)d_in[0];
    const float* Wq = (const float*)d_in[1];
    const float* Wk = (const float*)d_in[2];
    const float* Wv = (const float*)d_in[3];
    const float* Wo = (const float*)d_in[4];
    float* out = (float*)d_out;

    __half *xs, *Wh, *Qs, *Ks, *Vs, *Ps, *VW;
    float* S;
    cudaGetSymbolAddress((void**)&xs, g_xs);
    cudaGetSymbolAddress((void**)&Wh, g_Wh);
    cudaGetSymbolAddress((void**)&Qs, g_Qs);
    cudaGetSymbolAddress((void**)&Ks, g_Ks);
    cudaGetSymbolAddress((void**)&Vs, g_Vs);
    cudaGetSymbolAddress((void**)&S,  g_S);
    cudaGetSymbolAddress((void**)&Ps, g_Ps);
    cudaGetSymbolAddress((void**)&VW, g_VW);

    cudaFuncSetAttribute(gemm_mma<0,1>,   cudaFuncAttributeMaxDynamicSharedMemorySize, SMEM_SZ);
    cudaFuncSetAttribute(gemm_qkv,        cudaFuncAttributeMaxDynamicSharedMemorySize, SMEM_SZ);
    cudaFuncSetAttribute(gemm_scores_vwo, cudaFuncAttributeMaxDynamicSharedMemorySize, SMEM_SZ);

    const float scale = 1.0f / sqrtf((float)D_MODEL);
    const long sBSS = (long)SEQ * SEQ;          // 4194304
    const long sSD  = (long)SEQ * D_MODEL;      // 4194304

    // all conversions in one launch (x + 4 weights, elementwise fp32->fp16)
    convall_kernel<<<24576, 256>>>(x, Wq, Wk, Wv, Wo, xs, Wh);

    const dim3 gQKV(D_MODEL / 128, MROWS / 128, 3);    // (16, 32, 3) = 1536 CTAs
    const dim3 gFused(SEQ / 128, SEQ / 128, 4);        // (16, 16, 4) = 1024 CTAs
    const dim3 gFinal(D_MODEL / 128, SEQ / 128, BATCH);// (16, 16, 2) = 512 CTAs

    // Q, K, V projections in one launch
    gemm_qkv<<<gQKV, GTHR, SMEM_SZ>>>(xs, Wh, Qs, Ks, Vs);
    // fused: scores (z=0,1) and V@Wo (z=2,3) in one 1024-CTA launch
    gemm_scores_vwo<<<gFused, GTHR, SMEM_SZ>>>(Qs, Ks, Vs, Wh + 3 * WELEMS,
                                               S, VW, scale);
    // softmax -> P fp16
    softmax_kernel<<<BATCH * SEQ, 256>>>(S, Ps);
    // out = P @ (V@Wo)   (VW is [s][d] = [k][n]: trans path, fp32 epi)
    gemm_mma<0,1><<<gFinal, GTHR, SMEM_SZ>>>(Ps, VW,
                                             out, nullptr, sBSS, sSD, sSD, 1.0f);
}

// round 14
// speedup vs baseline: 1.1725x; 1.0183x over previous
#include <cuda_runtime.h>
#include <cuda_fp16.h>
#include <math.h>
#include <stdint.h>

#define D_MODEL 2048
#define BATCH   2
#define SEQ     2048
#define MROWS   (BATCH * SEQ)                 // 4096
#define ELEMS   ((size_t)MROWS * D_MODEL)     // 8388608
#define WELEMS  ((size_t)D_MODEL * D_MODEL)   // 4194304

// ---------------------------------------------------------------------------
// Device scratch (allocation-free contract) — all single fp16
// ---------------------------------------------------------------------------
__device__ __half g_xs[ELEMS];                      // x fp16
__device__ __half g_Wh[4 * WELEMS];                 // W fp16, [k][n] (as given)
__device__ __half g_Qs[ELEMS];                      // Q row-major
__device__ __half g_Ks[ELEMS];                      // K row-major
__device__ __half g_Vs[ELEMS];                      // V row-major [b][s][d]
__device__ float  g_S [(size_t)BATCH * SEQ * SEQ];  // scores fp32
__device__ __half g_Ps[(size_t)BATCH * SEQ * SEQ];  // softmax(P)
__device__ __half g_VW[ELEMS];                      // V @ Wo, [b][s][d]

// ---------------------------------------------------------------------------
// Helpers
// ---------------------------------------------------------------------------
__device__ __forceinline__ uint32_t s2u(const void* p) {
    return (uint32_t)__cvta_generic_to_shared(p);
}
__device__ __forceinline__ void cp16(uint32_t dst, const void* src) {
    asm volatile("cp.async.cg.shared.global [%0], [%1], 16;\n"
                 :: "r"(dst), "l"(__cvta_generic_to_global(src)));
}
__device__ __forceinline__ void cp_commit() { asm volatile("cp.async.commit_group;"); }
template<int N> __device__ __forceinline__ void cp_wait() {
    asm volatile("cp.async.wait_group %0;" :: "n"(N));
}
__device__ __forceinline__ void ldm_x4(uint32_t* r, uint32_t addr) {
    asm volatile("ldmatrix.sync.aligned.m8n8.x4.shared.b16 {%0,%1,%2,%3}, [%4];"
                 : "=r"(r[0]), "=r"(r[1]), "=r"(r[2]), "=r"(r[3]) : "r"(addr));
}
__device__ __forceinline__ void ldm_x4_t(uint32_t* r, uint32_t addr) {
    asm volatile("ldmatrix.sync.aligned.m8n8.x4.trans.shared.b16 {%0,%1,%2,%3}, [%4];"
                 : "=r"(r[0]), "=r"(r[1]), "=r"(r[2]), "=r"(r[3]) : "r"(addr));
}
__device__ __forceinline__ void mma_f16(float* d, const uint32_t* a,
                                        uint32_t b0, uint32_t b1) {
    asm volatile(
        "mma.sync.aligned.m16n8k16.row.col.f32.f16.f16.f32 "
        "{%0,%1,%2,%3}, {%4,%5,%6,%7}, {%8,%9}, {%0,%1,%2,%3};"
        : "+f"(d[0]), "+f"(d[1]), "+f"(d[2]), "+f"(d[3])
        : "r"(a[0]), "r"(a[1]), "r"(a[2]), "r"(a[3]), "r"(b0), "r"(b1));
}
__device__ __forceinline__ unsigned short h1(float v) {
    __half hh = __float2half_rn(v);
    return *reinterpret_cast<unsigned short*>(&hh);
}

// ---------------------------------------------------------------------------
// Tiling:
// CTA tile (64*MT) x 128, 512 threads = 16 warps (4 M-warps x 4 N-warps),
// warp tile (16*MT) x 32. K-chunk 32, 4-stage cp.async, 1 CTA/SM.
// A smem: 64*MT rows x (64B data + 16B pad = 80B).
// B smem TRANSB=0 (K-major, rows=n): 128 rows x 80B.
// B smem TRANSB=1 (N-major [k][n], rows=k): 32 rows x (256B + 16B pad = 272B).
// ---------------------------------------------------------------------------
#define KC      32
#define STAGES  4
#define ROWA    80
#define ROWBT   272
#define TILE_BT (KC * ROWBT)        // 8704
#define TILE_B0 (128 * ROWA)        // 10240
#define NCH     (2048 / KC)         // 64
#define GTHR    512

template<int MT, int TRANSB>
struct Cfg {
    static const int TILE_A = 64 * MT * ROWA;
    static const int TILE_B = TRANSB ? TILE_BT : TILE_B0;
    static const int STG    = TILE_A + TILE_B;
    static const int SMEM   = STAGES * STG;
};

struct MmaCtx {
    float acc[2][4][4];
};

template<int MT, int TRANSB>
__device__ __forceinline__ void gemm_mainloop(
    MmaCtx& ctx, uint32_t sb, int tid, int wm, int wn, int lane,
    const __half* A0, const __half* B0, long rowA0, long colB0)
{
    const int STG    = Cfg<MT, TRANSB>::STG;
    const int TILE_A = Cfg<MT, TRANSB>::TILE_A;
    const int AROWS  = 64 * MT;

    const int lrA = tid >> 2;
    const int lsA = tid & 3;
    const int lrB = TRANSB ? (tid >> 4) : (tid >> 2);
    const int lsB = TRANSB ? (tid & 15) : (tid & 3);

    auto load_chunk = [&](int chunk, int stage) {
        const int k0 = chunk * KC;
        const uint32_t base = sb + (uint32_t)stage * STG;
        if (MT == 2 || lrA < AROWS) {
            cp16(base + (uint32_t)(lrA * ROWA + lsA * 16),
                 A0 + (rowA0 + lrA) * 2048 + k0 + lsA * 8);
        }
        if (TRANSB) {
            cp16(base + TILE_A + (uint32_t)(lrB * ROWBT + lsB * 16),
                 B0 + (long)(k0 + lrB) * 2048 + colB0 + lsB * 8);
        } else {
            cp16(base + TILE_A + (uint32_t)(lrB * ROWA + lsB * 16),
                 B0 + (colB0 + lrB) * 2048 + k0 + lsB * 8);
        }
    };

    const int fr  = lane & 15;
    const int fc  = (lane >> 4) << 4;
    const uint32_t aoff = (uint32_t)((wm * 16 * MT + fr) * ROWA + fc);
    const uint32_t boff0 = (uint32_t)((wn * 32 + fr) * ROWA + fc);
    const int kr   = (lane & 7) + ((lane >> 4) << 3);
    const int nby  = ((lane >> 3) & 1) << 4;
    const uint32_t boff1 = (uint32_t)(kr * ROWBT + wn * 64 + nby);

    #pragma unroll
    for (int i = 0; i < MT; i++)
        #pragma unroll
        for (int j = 0; j < 4; j++)
            #pragma unroll
            for (int c = 0; c < 4; c++)
                ctx.acc[i][j][c] = 0.0f;

    load_chunk(0, 0); cp_commit();
    load_chunk(1, 1); cp_commit();
    load_chunk(2, 2); cp_commit();

    for (int i = 0; i < NCH; i++) {
        if (i < NCH - 2)       cp_wait<2>();
        else if (i == NCH - 2) cp_wait<1>();
        else                   cp_wait<0>();
        __syncthreads();

        if (i + STAGES - 1 < NCH) {
            load_chunk(i + STAGES - 1, (i + STAGES - 1) & (STAGES - 1));
            cp_commit();
        }

        const uint32_t base = sb + (uint32_t)(i & (STAGES - 1)) * STG;
        #pragma unroll
        for (int ks = 0; ks < 2; ks++) {
            uint32_t aa[MT][4], bb[2][4];
            #pragma unroll
            for (int mf = 0; mf < MT; mf++) {
                uint32_t ad = base + aoff + (uint32_t)(mf * 16 * ROWA + ks * 32);
                ldm_x4(aa[mf], ad);
            }
            #pragma unroll
            for (int nf = 0; nf < 2; nf++) {
                if (TRANSB) {
                    uint32_t bd = base + TILE_A + boff1
                                + (uint32_t)(ks * 16 * ROWBT + nf * 32);
                    ldm_x4_t(bb[nf], bd);
                } else {
                    uint32_t bd = base + TILE_A + boff0
                                + (uint32_t)(nf * 16 * ROWA + ks * 32);
                    ldm_x4(bb[nf], bd);
                }
            }
            #pragma unroll
            for (int mf = 0; mf < MT; mf++)
                #pragma unroll
                for (int j = 0; j < 4; j++) {
                    const int nf = j >> 1, o = j & 1;
                    mma_f16(ctx.acc[mf][j], aa[mf], bb[nf][o], bb[nf][o + 2]);
                }
        }
    }
    __syncthreads();
}

// ---------------------------------------------------------------------------
// Epilogue helpers
// ---------------------------------------------------------------------------
template<int MT>
__device__ __forceinline__ void epi_f32(const MmaCtx& ctx, float* C,
                                        long rowA0, long colB0,
                                        int wm, int wn, int lane, float alpha)
{
    const int er = lane >> 2;
    const int ec = (lane & 3) << 1;
    #pragma unroll
    for (int mf = 0; mf < MT; mf++) {
        const long m0 = rowA0 + wm * 16 * MT + mf * 16 + er;
        #pragma unroll
        for (int j = 0; j < 4; j++) {
            const long n = colB0 + wn * 32 + j * 8 + ec;
            float2 v0 = make_float2(alpha * ctx.acc[mf][j][0], alpha * ctx.acc[mf][j][1]);
            float2 v1 = make_float2(alpha * ctx.acc[mf][j][2], alpha * ctx.acc[mf][j][3]);
            *reinterpret_cast<float2*>(C + m0 * 2048 + n)       = v0;
            *reinterpret_cast<float2*>(C + (m0 + 8) * 2048 + n) = v1;
        }
    }
}

template<int MT>
__device__ __forceinline__ void epi_f16(const MmaCtx& ctx, unsigned short* C,
                                        long rowA0, long colB0,
                                        int wm, int wn, int lane)
{
    const int er = lane >> 2;
    const int ec = (lane & 3) << 1;
    #pragma unroll
    for (int mf = 0; mf < MT; mf++) {
        const long m0 = rowA0 + wm * 16 * MT + mf * 16 + er;
        #pragma unroll
        for (int j = 0; j < 4; j++) {
            const long n = colB0 + wn * 32 + j * 8 + ec;
            ushort2 v0 = make_ushort2(h1(ctx.acc[mf][j][0]), h1(ctx.acc[mf][j][1]));
            ushort2 v1 = make_ushort2(h1(ctx.acc[mf][j][2]), h1(ctx.acc[mf][j][3]));
            *reinterpret_cast<ushort2*>(C + m0 * 2048 + n)       = v0;
            *reinterpret_cast<ushort2*>(C + (m0 + 8) * 2048 + n) = v1;
        }
    }
}

// ---------------------------------------------------------------------------
// Generic GEMM kernel (EPI: 0 = fp32*alpha -> Cf ; 2 = fp16 -> Ch)
// ---------------------------------------------------------------------------
template<int EPI, int TRANSB, int MT>
__global__ void __launch_bounds__(GTHR, 1)
gemm_mma(const __half* __restrict__ A, const __half* __restrict__ B,
         float* __restrict__ Cf, __half* __restrict__ Ch,
         long sA, long sB, long sC, float alpha)
{
    extern __shared__ char smem[];
    const uint32_t sb = s2u(smem);
    const int tid  = threadIdx.x;
    const int warp = tid >> 5;
    const int lane = tid & 31;
    const int wm   = warp & 3;
    const int wn   = warp >> 2;

    const long rowA0 = (long)blockIdx.y * (64 * MT);
    const long colB0 = (long)blockIdx.x * 128;

    MmaCtx ctx;
    gemm_mainloop<MT, TRANSB>(ctx, sb, tid, wm, wn, lane,
                              A + (long)blockIdx.z * sA, B + (long)blockIdx.z * sB,
                              rowA0, colB0);

    if (EPI == 0)
        epi_f32<MT>(ctx, Cf + (long)blockIdx.z * sC, rowA0, colB0, wm, wn, lane, alpha);
    else
        epi_f16<MT>(ctx, (unsigned short*)Ch + (long)blockIdx.z * sC,
                    rowA0, colB0, wm, wn, lane);
}

// ---------------------------------------------------------------------------
// Merged Q/K/V projection kernel: grid.z = weight index (0=Q, 1=K, 2=V).
// ---------------------------------------------------------------------------
__global__ void __launch_bounds__(GTHR, 1)
gemm_qkv(const __half* __restrict__ xs, const __half* __restrict__ Wh,
         __half* __restrict__ Qs, __half* __restrict__ Ks,
         __half* __restrict__ Vs)
{
    extern __shared__ char smem[];
    const uint32_t sb = s2u(smem);
    const int tid  = threadIdx.x;
    const int warp = tid >> 5;
    const int lane = tid & 31;
    const int wm   = warp & 3;
    const int wn   = warp >> 2;
    const int z    = blockIdx.z;

    const long rowA0 = (long)blockIdx.y * 128;
    const long colB0 = (long)blockIdx.x * 128;

    MmaCtx ctx;
    gemm_mainloop<2, 1>(ctx, sb, tid, wm, wn, lane,
                        xs, Wh + (long)z * (long)WELEMS, rowA0, colB0);

    unsigned short* C = (unsigned short*)(z == 0 ? Qs : (z == 1 ? Ks : Vs));
    epi_f16<2>(ctx, C, rowA0, colB0, wm, wn, lane);
}

// ---------------------------------------------------------------------------
// Fused scores + V@Wo kernel, grid (16,16,4):
//   z=0,1: scores[z] = scale * Q[z] @ K[z]^T   (TRANSB=0, fp32 epi)
//   z=2,3: VW[z-2]   = V[z-2] @ Wo             (TRANSB=1, fp16 epi)
// ---------------------------------------------------------------------------
__global__ void __launch_bounds__(GTHR, 1)
gemm_scores_vwo(const __half* __restrict__ Qs, const __half* __restrict__ Ks,
                const __half* __restrict__ Vs, const __half* __restrict__ Wo,
                float* __restrict__ S, __half* __restrict__ VW, float scale)
{
    extern __shared__ char smem[];
    const uint32_t sb = s2u(smem);
    const int tid  = threadIdx.x;
    const int warp = tid >> 5;
    const int lane = tid & 31;
    const int wm   = warp & 3;
    const int wn   = warp >> 2;
    const int z    = blockIdx.z;

    const long rowA0 = (long)blockIdx.y * 128;
    const long colB0 = (long)blockIdx.x * 128;
    const long sSD  = (long)SEQ * D_MODEL;
    const long sBSS = (long)SEQ * SEQ;

    MmaCtx ctx;
    if (z < 2) {
        gemm_mainloop<2, 0>(ctx, sb, tid, wm, wn, lane,
                            Qs + z * sSD, Ks + z * sSD, rowA0, colB0);
        epi_f32<2>(ctx, S + z * sBSS, rowA0, colB0, wm, wn, lane, scale);
    } else {
        gemm_mainloop<2, 1>(ctx, sb, tid, wm, wn, lane,
                            Vs + (z - 2) * sSD, Wo, rowA0, colB0);
        epi_f16<2>(ctx, (unsigned short*)VW + (z - 2) * sSD, rowA0, colB0, wm, wn, lane);
    }
}

// ---------------------------------------------------------------------------
// Merged conversion kernel with 4 independent float4 loads per thread:
//   blocks [0, 2048):      x fp32 -> fp16      (4096 floats per block)
//   blocks [2048, 6144):   W fp32 -> fp16      (1024 blocks per weight)
// ---------------------------------------------------------------------------
__global__ void __launch_bounds__(256)
convall_kernel(const float* __restrict__ x,
               const float* __restrict__ Wq, const float* __restrict__ Wk,
               const float* __restrict__ Wv, const float* __restrict__ Wo,
               __half* __restrict__ xs, __half* __restrict__ Wh)
{
    const int bid = blockIdx.x;
    const float* src;
    unsigned short* dst;
    size_t base;                         // in float4 units
    if (bid < 2048) {
        src = x; dst = (unsigned short*)xs;
        base = (size_t)bid * 1024;
    } else {
        const int t = bid - 2048;
        const int w = t >> 10;           // weight index 0..3
        src = (w == 0) ? Wq : (w == 1) ? Wk : (w == 2) ? Wv : Wo;
        dst = (unsigned short*)(Wh + (size_t)w * WELEMS);
        base = (size_t)(t & 1023) * 1024;
    }
    float4 v[4];
    #pragma unroll
    for (int p = 0; p < 4; p++)
        v[p] = *reinterpret_cast<const float4*>(src + (base + p * 256 + threadIdx.x) * 4);
    #pragma unroll
    for (int p = 0; p < 4; p++) {
        ushort4 H;
        H.x = h1(v[p].x); H.y = h1(v[p].y); H.z = h1(v[p].z); H.w = h1(v[p].w);
        *reinterpret_cast<ushort4*>(dst + (base + p * 256 + threadIdx.x) * 4) = H;
    }
}

// ---------------------------------------------------------------------------
// Row softmax (fp32 in) -> P fp16. One block per row of 2048.
// ---------------------------------------------------------------------------
__global__ void __launch_bounds__(256)
softmax_kernel(const float* __restrict__ S, __half* __restrict__ P)
{
    const float4* row = reinterpret_cast<const float4*>(S + (size_t)blockIdx.x * SEQ);
    const int tid = threadIdx.x, lane = tid & 31, wid = tid >> 5;

    float4 a = row[tid];
    float4 b = row[tid + 256];

    float m = fmaxf(fmaxf(fmaxf(a.x, a.y), fmaxf(a.z, a.w)),
                    fmaxf(fmaxf(b.x, b.y), fmaxf(b.z, b.w)));
    #pragma unroll
    for (int o = 16; o > 0; o >>= 1) m = fmaxf(m, __shfl_xor_sync(~0u, m, o));

    __shared__ float redm[8], reds[8];
    if (lane == 0) redm[wid] = m;
    __syncthreads();
    float bm = fmaxf(fmaxf(fmaxf(redm[0], redm[1]), fmaxf(redm[2], redm[3])),
                     fmaxf(fmaxf(redm[4], redm[5]), fmaxf(redm[6], redm[7])));

    a.x = expf(a.x - bm); a.y = expf(a.y - bm); a.z = expf(a.z - bm); a.w = expf(a.w - bm);
    b.x = expf(b.x - bm); b.y = expf(b.y - bm); b.z = expf(b.z - bm); b.w = expf(b.w - bm);

    float sm = a.x + a.y + a.z + a.w + b.x + b.y + b.z + b.w;
    #pragma unroll
    for (int o = 16; o > 0; o >>= 1) sm += __shfl_xor_sync(~0u, sm, o);
    if (lane == 0) reds[wid] = sm;
    __syncthreads();
    float bs = reds[0] + reds[1] + reds[2] + reds[3] + reds[4] + reds[5] + reds[6] + reds[7];
    float inv = 1.0f / bs;

    const size_t base = (size_t)blockIdx.x * SEQ;
    unsigned short* PP = (unsigned short*)P;
    ushort4 H;
    H.x = h1(a.x * inv); H.y = h1(a.y * inv);
    H.z = h1(a.z * inv); H.w = h1(a.w * inv);
    *reinterpret_cast<ushort4*>(PP + base + tid * 4) = H;
    H.x = h1(b.x * inv); H.y = h1(b.y * inv);
    H.z = h1(b.z * inv); H.w = h1(b.w * inv);
    *reinterpret_cast<ushort4*>(PP + base + (tid + 256) * 4) = H;
}

// ---------------------------------------------------------------------------
// Launch
// ---------------------------------------------------------------------------
extern "C" void kernel_launch(void* const* d_in, const int* in_sizes, int n_in,
                              void* d_out, int out_size)
{
    (void)in_sizes; (void)n_in; (void)out_size;
    const float* x  = (const float*)d_in[0];
    const float* Wq = (const float*)d_in[1];
    const float* Wk = (const float*)d_in[2];
    const float* Wv = (const float*)d_in[3];
    const float* Wo = (const float*)d_in[4];
    float* out = (float*)d_out;

    __half *xs, *Wh, *Qs, *Ks, *Vs, *Ps, *VW;
    float* S;
    cudaGetSymbolAddress((void**)&xs, g_xs);
    cudaGetSymbolAddress((void**)&Wh, g_Wh);
    cudaGetSymbolAddress((void**)&Qs, g_Qs);
    cudaGetSymbolAddress((void**)&Ks, g_Ks);
    cudaGetSymbolAddress((void**)&Vs, g_Vs);
    cudaGetSymbolAddress((void**)&S,  g_S);
    cudaGetSymbolAddress((void**)&Ps, g_Ps);
    cudaGetSymbolAddress((void**)&VW, g_VW);

    const int SM_BIG   = Cfg<2, 0>::SMEM;   // 81920
    const int SM_FINAL = Cfg<1, 1>::SMEM;   // 55296

    cudaFuncSetAttribute(gemm_mma<0,1,1>, cudaFuncAttributeMaxDynamicSharedMemorySize, SM_FINAL);
    cudaFuncSetAttribute(gemm_qkv,        cudaFuncAttributeMaxDynamicSharedMemorySize, SM_BIG);
    cudaFuncSetAttribute(gemm_scores_vwo, cudaFuncAttributeMaxDynamicSharedMemorySize, SM_BIG);

    const float scale = 1.0f / sqrtf((float)D_MODEL);
    const long sBSS = (long)SEQ * SEQ;          // 4194304
    const long sSD  = (long)SEQ * D_MODEL;      // 4194304

    // all conversions in one launch (x + 4 weights, 4x float4 per thread)
    convall_kernel<<<6144, 256>>>(x, Wq, Wk, Wv, Wo, xs, Wh);

    const dim3 gQKV(D_MODEL / 128, MROWS / 128, 3);    // (16, 32, 3) = 1536 CTAs
    const dim3 gFused(SEQ / 128, SEQ / 128, 4);        // (16, 16, 4) = 1024 CTAs
    const dim3 gFinal(D_MODEL / 128, SEQ / 64, BATCH); // (16, 32, 2) = 1024 CTAs

    // Q, K, V projections in one launch
    gemm_qkv<<<gQKV, GTHR, SM_BIG>>>(xs, Wh, Qs, Ks, Vs);
    // fused: scores (z=0,1) and V@Wo (z=2,3) in one 1024-CTA launch
    gemm_scores_vwo<<<gFused, GTHR, SM_BIG>>>(Qs, Ks, Vs, Wh + 3 * WELEMS,
                                              S, VW, scale);
    // softmax -> P fp16
    softmax_kernel<<<BATCH * SEQ, 256>>>(S, Ps);
    // out = P @ (V@Wo)   (M-tile 64 -> 1024 CTAs, tail ~1%)
    gemm_mma<0,1,1><<<gFinal, GTHR, SM_FINAL>>>(Ps, VW,
                                                out, nullptr, sBSS, sSD, sSD, 1.0f);
}